// round 1
// baseline (speedup 1.0000x reference)
#include <cuda_runtime.h>
#include <math.h>

#define S_LEN 2048
#define HID   3584
#define NHQ   28
#define NKV   4
#define DH    128
#define DKV   (NKV * DH)   // 512
#define N_REP (NHQ / NKV)  // 7

// Scratch (allocation-free rule: __device__ globals)
__device__ float g_Q[S_LEN * HID];
__device__ float g_K[S_LEN * DKV];
__device__ float g_V[S_LEN * DKV];
__device__ float g_AO[S_LEN * HID];

// ---------------------------------------------------------------------------
// SGEMM: C[M,N] = A[M,K] @ B[N,K]^T + bias[N]
// BM=BN=128, BK=8, 256 threads, 8x8 microtile per thread.
// ---------------------------------------------------------------------------
__global__ __launch_bounds__(256) void sgemm_nt(
    const float* __restrict__ A, const float* __restrict__ B,
    const float* __restrict__ bias, float* __restrict__ C,
    int M, int N, int K)
{
    __shared__ __align__(16) float As[8][128];  // transposed: As[k][m]
    __shared__ __align__(16) float Bs[8][128];  // transposed: Bs[k][n]

    const int tid = threadIdx.x;
    const int tx = tid & 15;          // 0..15  -> N dim
    const int ty = tid >> 4;          // 0..15  -> M dim
    const int bm = blockIdx.y * 128;
    const int bn = blockIdx.x * 128;

    // global->smem load mapping: each thread loads one float4 of A and of B
    const int lr = tid >> 1;          // 0..127 row within tile
    const int lc = (tid & 1) * 4;     // 0 or 4 (col within BK=8)
    const float* Ag = A + (size_t)(bm + lr) * K + lc;
    const float* Bg = B + (size_t)(bn + lr) * K + lc;

    float acc[8][8];
#pragma unroll
    for (int i = 0; i < 8; i++)
#pragma unroll
        for (int j = 0; j < 8; j++) acc[i][j] = 0.0f;

    for (int k0 = 0; k0 < K; k0 += 8) {
        float4 a4 = *(const float4*)(Ag + k0);
        float4 b4 = *(const float4*)(Bg + k0);
        __syncthreads();
        As[lc + 0][lr] = a4.x; As[lc + 1][lr] = a4.y;
        As[lc + 2][lr] = a4.z; As[lc + 3][lr] = a4.w;
        Bs[lc + 0][lr] = b4.x; Bs[lc + 1][lr] = b4.y;
        Bs[lc + 2][lr] = b4.z; Bs[lc + 3][lr] = b4.w;
        __syncthreads();
#pragma unroll
        for (int kk = 0; kk < 8; kk++) {
            float4 a0 = *(const float4*)&As[kk][ty * 8];
            float4 a1 = *(const float4*)&As[kk][ty * 8 + 4];
            float4 b0 = *(const float4*)&Bs[kk][tx * 8];
            float4 b1 = *(const float4*)&Bs[kk][tx * 8 + 4];
            float a[8] = {a0.x, a0.y, a0.z, a0.w, a1.x, a1.y, a1.z, a1.w};
            float b[8] = {b0.x, b0.y, b0.z, b0.w, b1.x, b1.y, b1.z, b1.w};
#pragma unroll
            for (int i = 0; i < 8; i++)
#pragma unroll
                for (int j = 0; j < 8; j++)
                    acc[i][j] += a[i] * b[j];
        }
    }

    float bvals[8];
#pragma unroll
    for (int j = 0; j < 8; j++)
        bvals[j] = bias ? bias[bn + tx * 8 + j] : 0.0f;

#pragma unroll
    for (int i = 0; i < 8; i++) {
        const int row = bm + ty * 8 + i;
        float* Cr = C + (size_t)row * N + bn + tx * 8;
        float4 o0, o1;
        o0.x = acc[i][0] + bvals[0]; o0.y = acc[i][1] + bvals[1];
        o0.z = acc[i][2] + bvals[2]; o0.w = acc[i][3] + bvals[3];
        o1.x = acc[i][4] + bvals[4]; o1.y = acc[i][5] + bvals[5];
        o1.z = acc[i][6] + bvals[6]; o1.w = acc[i][7] + bvals[7];
        *(float4*)(Cr) = o0;
        *(float4*)(Cr + 4) = o1;
    }
}

// ---------------------------------------------------------------------------
// RoPE (mRoPE collapses to t=0 slice since pos identical across 3 axes).
// In-place on Q (28 heads) and K (4 heads). One block per sequence position.
// ---------------------------------------------------------------------------
__global__ __launch_bounds__(256) void rope_kernel(
    float* __restrict__ Q, float* __restrict__ Kv,
    const float* __restrict__ cosb, const float* __restrict__ sinb)
{
    const int s = blockIdx.x;
    const float* cs = cosb + (size_t)s * DH;   // cos[0,0,s,:]
    const float* sn = sinb + (size_t)s * DH;
    const int tid = threadIdx.x;
    // 32 heads total (28 Q + 4 K), 64 rotation pairs per head
    for (int i = tid; i < 32 * 64; i += 256) {
        const int head = i >> 6;
        const int d = i & 63;
        float* p = (head < NHQ)
                     ? Q + (size_t)s * HID + head * DH
                     : Kv + (size_t)s * DKV + (head - NHQ) * DH;
        const float c1 = cs[d], c2 = cs[d + 64];
        const float s1 = sn[d], s2 = sn[d + 64];
        const float x1 = p[d], x2 = p[d + 64];
        p[d]      = x1 * c1 - x2 * s1;
        p[d + 64] = x2 * c2 + x1 * s2;
    }
}

// ---------------------------------------------------------------------------
// Causal flash attention, fp32. Grid (S/64, NHQ), 256 threads.
// Per block: 64 queries of one head. Online softmax over 64-key tiles.
// ---------------------------------------------------------------------------
#define ATTN_SMEM_FLOATS (8192 + 8192 + 8192 + 64*65 + 64*16 + 192)
#define ATTN_SMEM_BYTES  (ATTN_SMEM_FLOATS * 4)

__global__ __launch_bounds__(256) void attn_kernel(
    const float* __restrict__ Q, const float* __restrict__ K,
    const float* __restrict__ V, float* __restrict__ O)
{
    extern __shared__ __align__(16) float sm[];
    float* QT   = sm;                 // [128][64] transposed Q tile
    float* KT   = sm + 8192;          // [128][64] transposed K tile
    float* VS   = sm + 16384;         // [64][128] natural V tile
    float* PS   = sm + 24576;         // [64][65]  probs (padded)
    float* RED  = sm + 24576 + 4160;  // [64][16]  reduction scratch
    float* Mrow = RED + 1024;         // [64]
    float* Lrow = Mrow + 64;          // [64]
    float* Arow = Lrow + 64;          // [64]

    const int tid = threadIdx.x;
    const int tx = tid & 15;
    const int ty = tid >> 4;
    const int q0 = blockIdx.x * 64;
    const int h  = blockIdx.y;
    const int kvh = h / N_REP;
    const int r0 = ty * 4;
    const int c0 = tx * 4;

    // ---- load Q tile transposed: QT[d][r] ----
    {
        const int r = tid & 63;
        const int c4b = tid >> 6;     // 0..3
        const float* qg = Q + (size_t)(q0 + r) * HID + h * DH;
#pragma unroll
        for (int it = 0; it < 8; it++) {
            const int d0 = (c4b + it * 4) * 4;
            float4 v = *(const float4*)(qg + d0);
            QT[(d0 + 0) * 64 + r] = v.x;
            QT[(d0 + 1) * 64 + r] = v.y;
            QT[(d0 + 2) * 64 + r] = v.z;
            QT[(d0 + 3) * 64 + r] = v.w;
        }
    }
    if (tid < 64) { Mrow[tid] = -3.0e38f; Lrow[tid] = 0.0f; }

    float oacc[4][8];
#pragma unroll
    for (int i = 0; i < 4; i++)
#pragma unroll
        for (int j = 0; j < 8; j++) oacc[i][j] = 0.0f;

    const float scale = 0.08838834764831845f;  // 1/sqrt(128)
    const int nkt = q0 / 64 + 1;               // causal: tiles up to diagonal

    for (int kt = 0; kt < nkt; kt++) {
        const int k0 = kt * 64;
        __syncthreads();  // previous iteration's PS/VS reads done

        // ---- load K tile transposed: KT[d][c] ----
        {
            const int r = tid & 63;
            const int c4b = tid >> 6;
            const float* kg = K + (size_t)(k0 + r) * DKV + kvh * DH;
#pragma unroll
            for (int it = 0; it < 8; it++) {
                const int d0 = (c4b + it * 4) * 4;
                float4 v = *(const float4*)(kg + d0);
                KT[(d0 + 0) * 64 + r] = v.x;
                KT[(d0 + 1) * 64 + r] = v.y;
                KT[(d0 + 2) * 64 + r] = v.z;
                KT[(d0 + 3) * 64 + r] = v.w;
            }
        }
        // ---- load V tile natural: VS[kk][d] (coalesced) ----
        {
            const int vr = tid >> 5;          // 0..7, +8*it
            const int vc = (tid & 31) * 4;
#pragma unroll
            for (int it = 0; it < 8; it++) {
                const int row = vr + it * 8;
                float4 v = *(const float4*)(V + (size_t)(k0 + row) * DKV + kvh * DH + vc);
                *(float4*)&VS[row * 128 + vc] = v;
            }
        }
        __syncthreads();

        // ---- S = Q K^T (4x4 microtile) ----
        float sacc[4][4];
#pragma unroll
        for (int i = 0; i < 4; i++)
#pragma unroll
            for (int j = 0; j < 4; j++) sacc[i][j] = 0.0f;

#pragma unroll 8
        for (int k = 0; k < 128; k++) {
            float4 qa = *(const float4*)&QT[k * 64 + r0];
            float4 ka = *(const float4*)&KT[k * 64 + c0];
            float qv[4] = {qa.x, qa.y, qa.z, qa.w};
            float kv[4] = {ka.x, ka.y, ka.z, ka.w};
#pragma unroll
            for (int i = 0; i < 4; i++)
#pragma unroll
                for (int j = 0; j < 4; j++)
                    sacc[i][j] += qv[i] * kv[j];
        }

        // ---- scale + causal mask + partial row max ----
#pragma unroll
        for (int i = 0; i < 4; i++) {
            float mx = -3.0e38f;
#pragma unroll
            for (int j = 0; j < 4; j++) {
                float s = sacc[i][j] * scale;
                if (k0 + c0 + j > q0 + r0 + i) s = -3.0e38f;
                sacc[i][j] = s;
                mx = fmaxf(mx, s);
            }
            RED[(r0 + i) * 16 + tx] = mx;
        }
        __syncthreads();
        if (tid < 64) {
            float mt = RED[tid * 16];
#pragma unroll
            for (int j = 1; j < 16; j++) mt = fmaxf(mt, RED[tid * 16 + j]);
            const float mold = Mrow[tid];
            const float mnew = fmaxf(mold, mt);
            Arow[tid] = __expf(mold - mnew);
            Mrow[tid] = mnew;
        }
        __syncthreads();

        // ---- exp, write P, partial row sums ----
#pragma unroll
        for (int i = 0; i < 4; i++) {
            const float mr = Mrow[r0 + i];
            float rs = 0.0f;
#pragma unroll
            for (int j = 0; j < 4; j++) {
                const float p = __expf(sacc[i][j] - mr);
                PS[(r0 + i) * 65 + c0 + j] = p;
                rs += p;
            }
            RED[(r0 + i) * 16 + tx] = rs;
        }
        __syncthreads();
        if (tid < 64) {
            float s = 0.0f;
#pragma unroll
            for (int j = 0; j < 16; j++) s += RED[tid * 16 + j];
            Lrow[tid] = Lrow[tid] * Arow[tid] + s;
        }

        // ---- rescale O accumulators ----
#pragma unroll
        for (int i = 0; i < 4; i++) {
            const float al = Arow[r0 + i];
#pragma unroll
            for (int j = 0; j < 8; j++) oacc[i][j] *= al;
        }

        // ---- O += P @ V ----
#pragma unroll 4
        for (int kk = 0; kk < 64; kk++) {
            float p[4];
#pragma unroll
            for (int i = 0; i < 4; i++) p[i] = PS[(r0 + i) * 65 + kk];
            float4 v0 = *(const float4*)&VS[kk * 128 + tx * 8];
            float4 v1 = *(const float4*)&VS[kk * 128 + tx * 8 + 4];
            float v[8] = {v0.x, v0.y, v0.z, v0.w, v1.x, v1.y, v1.z, v1.w};
#pragma unroll
            for (int i = 0; i < 4; i++)
#pragma unroll
                for (int j = 0; j < 8; j++)
                    oacc[i][j] += p[i] * v[j];
        }
    }

    __syncthreads();  // final Lrow updates visible
#pragma unroll
    for (int i = 0; i < 4; i++) {
        const float inv = 1.0f / Lrow[r0 + i];
        float* og = O + (size_t)(q0 + r0 + i) * HID + h * DH + tx * 8;
        float4 o0, o1;
        o0.x = oacc[i][0] * inv; o0.y = oacc[i][1] * inv;
        o0.z = oacc[i][2] * inv; o0.w = oacc[i][3] * inv;
        o1.x = oacc[i][4] * inv; o1.y = oacc[i][5] * inv;
        o1.z = oacc[i][6] * inv; o1.w = oacc[i][7] * inv;
        *(float4*)(og) = o0;
        *(float4*)(og + 4) = o1;
    }
}

// ---------------------------------------------------------------------------
// Launch
// ---------------------------------------------------------------------------
extern "C" void kernel_launch(void* const* d_in, const int* in_sizes, int n_in,
                              void* d_out, int out_size)
{
    const float* hs   = (const float*)d_in[0];
    const float* Wq   = (const float*)d_in[1];
    const float* bq   = (const float*)d_in[2];
    const float* Wk   = (const float*)d_in[3];
    const float* bk   = (const float*)d_in[4];
    const float* Wv   = (const float*)d_in[5];
    const float* bv   = (const float*)d_in[6];
    const float* Wo   = (const float*)d_in[7];
    const float* cosb = (const float*)d_in[8];
    const float* sinb = (const float*)d_in[9];
    float* out = (float*)d_out;

    float *Qp, *Kp, *Vp, *AOp;
    cudaGetSymbolAddress((void**)&Qp, g_Q);
    cudaGetSymbolAddress((void**)&Kp, g_K);
    cudaGetSymbolAddress((void**)&Vp, g_V);
    cudaGetSymbolAddress((void**)&AOp, g_AO);

    cudaFuncSetAttribute(attn_kernel,
                         cudaFuncAttributeMaxDynamicSharedMemorySize,
                         ATTN_SMEM_BYTES);

    dim3 gQ(HID / 128, S_LEN / 128);   // 28 x 16
    dim3 gKV(DKV / 128, S_LEN / 128);  // 4 x 16

    sgemm_nt<<<gQ, 256>>>(hs, Wq, bq, Qp, S_LEN, HID, HID);
    sgemm_nt<<<gKV, 256>>>(hs, Wk, bk, Kp, S_LEN, DKV, HID);
    sgemm_nt<<<gKV, 256>>>(hs, Wv, bv, Vp, S_LEN, DKV, HID);

    rope_kernel<<<S_LEN, 256>>>(Qp, Kp, cosb, sinb);

    attn_kernel<<<dim3(S_LEN / 64, NHQ), 256, ATTN_SMEM_BYTES>>>(Qp, Kp, Vp, AOp);

    sgemm_nt<<<gQ, 256>>>(AOp, Wo, nullptr, out, S_LEN, HID, HID);
}

// round 4
// speedup vs baseline: 1.9992x; 1.9992x over previous
#include <cuda_runtime.h>
#include <cuda_bf16.h>
#include <stdint.h>
#include <math.h>

#define S_LEN 2048
#define HID   3584
#define NHQ   28
#define NKV   4
#define DH    128
#define DKV   (NKV * DH)   // 512
#define N_REP (NHQ / NKV)  // 7

// ---------------- scratch (__device__ globals; no allocs allowed) ----------
__device__ float g_Q[S_LEN * HID];
__device__ float g_K[S_LEN * DKV];
__device__ float g_V[S_LEN * DKV];
__device__ float g_AO[S_LEN * HID];

__device__ __nv_bfloat16 g_hs_h[S_LEN * HID],  g_hs_l[S_LEN * HID];
__device__ __nv_bfloat16 g_ao_h[S_LEN * HID],  g_ao_l[S_LEN * HID];
__device__ __nv_bfloat16 g_wq_h[HID * HID],    g_wq_l[HID * HID];
__device__ __nv_bfloat16 g_wo_h[HID * HID],    g_wo_l[HID * HID];
__device__ __nv_bfloat16 g_wk_h[DKV * HID],    g_wk_l[DKV * HID];
__device__ __nv_bfloat16 g_wv_h[DKV * HID],    g_wv_l[DKV * HID];

// ---------------- PTX helpers ---------------------------------------------
__device__ __forceinline__ uint32_t smem_u32(const void* p) {
    uint32_t a;
    asm("{ .reg .u64 t; cvta.to.shared.u64 t, %1; cvt.u32.u64 %0, t; }"
        : "=r"(a) : "l"(p));
    return a;
}
__device__ __forceinline__ void cp_async16(uint32_t dst, const void* src) {
    asm volatile("cp.async.cg.shared.global [%0], [%1], 16;\n"
                 :: "r"(dst), "l"(src) : "memory");
}
__device__ __forceinline__ void cp_commit() {
    asm volatile("cp.async.commit_group;" ::: "memory");
}
__device__ __forceinline__ void ldsm4(uint32_t* r, uint32_t addr) {
    asm volatile("ldmatrix.sync.aligned.m8n8.x4.shared.b16 {%0,%1,%2,%3}, [%4];\n"
                 : "=r"(r[0]), "=r"(r[1]), "=r"(r[2]), "=r"(r[3]) : "r"(addr));
}
__device__ __forceinline__ void mma16816(float* c, const uint32_t* a,
                                         const uint32_t* b) {
    asm volatile(
        "mma.sync.aligned.m16n8k16.row.col.f32.bf16.bf16.f32 "
        "{%0,%1,%2,%3}, {%4,%5,%6,%7}, {%8,%9}, {%0,%1,%2,%3};\n"
        : "+f"(c[0]), "+f"(c[1]), "+f"(c[2]), "+f"(c[3])
        : "r"(a[0]), "r"(a[1]), "r"(a[2]), "r"(a[3]), "r"(b[0]), "r"(b[1]));
}

// ---------------------------------------------------------------------------
// fp32 -> bf16 hi/lo split (elementwise)
// ---------------------------------------------------------------------------
__global__ __launch_bounds__(256) void split_bf16(
    const float* __restrict__ x, __nv_bfloat16* __restrict__ h,
    __nv_bfloat16* __restrict__ l, int n4)
{
    int i = blockIdx.x * blockDim.x + threadIdx.x;
    if (i >= n4) return;
    float4 v = ((const float4*)x)[i];
    float vv[4] = {v.x, v.y, v.z, v.w};
    __nv_bfloat16 hh[4], ll[4];
#pragma unroll
    for (int j = 0; j < 4; j++) {
        hh[j] = __float2bfloat16(vv[j]);
        ll[j] = __float2bfloat16(vv[j] - __bfloat162float(hh[j]));
    }
    __nv_bfloat162* hp = (__nv_bfloat162*)(h + i * 4);
    __nv_bfloat162* lp = (__nv_bfloat162*)(l + i * 4);
    hp[0] = __nv_bfloat162(hh[0], hh[1]); hp[1] = __nv_bfloat162(hh[2], hh[3]);
    lp[0] = __nv_bfloat162(ll[0], ll[1]); lp[1] = __nv_bfloat162(ll[2], ll[3]);
}

// ---------------------------------------------------------------------------
// bf16x3 HMMA GEMM: C[M,N] = A[M,K] @ B[N,K]^T + bias
// 256 thr = 8 warps (4x2), CTA tile 128x128, BK=32, double-buffered cp.async.
// smem tiles: rows padded to 80B (40 bf16) -> ldmatrix conflict-free.
// Stage layout: Ah(10240) Al(10240) Bh(10240) Bl(10240) = 40960B x 2 stages.
// ---------------------------------------------------------------------------
#define TPITCH 80
#define TILE_B 10240
#define STAGE_B 40960
#define GEMM_SMEM_BYTES (2 * STAGE_B)

__global__ __launch_bounds__(256, 2) void gemm_bf16x3(
    const __nv_bfloat16* __restrict__ Ah, const __nv_bfloat16* __restrict__ Al,
    const __nv_bfloat16* __restrict__ Bh, const __nv_bfloat16* __restrict__ Bl,
    const float* __restrict__ bias, float* __restrict__ C,
    int M, int N, int K)
{
    extern __shared__ __align__(128) char smem[];
    const uint32_t sb = smem_u32(smem);
    const int tid  = threadIdx.x;
    const int wid  = tid >> 5;
    const int lane = tid & 31;
    const int warp_m = wid & 3;          // 0..3 -> 32-row slice
    const int warp_n = wid >> 2;         // 0..1 -> 64-col slice
    const int bm = blockIdx.y * 128;
    const int bn = blockIdx.x * 128;
    const int nk = K >> 5;               // BK=32 chunks

    const __nv_bfloat16* srcs[4] = {Ah, Al, Bh, Bl};
    const int rowbase[4] = {bm, bm, bn, bn};

    // ---- stage loader: 2048 x 16B chunks, 8 per thread ----
    auto load_stage = [&](int s, int kb) {
#pragma unroll
        for (int i = 0; i < 8; ++i) {
            const int c    = (i << 8) + tid;
            const int tile = c >> 9;
            const int rem  = c & 511;
            const int r    = rem >> 2;
            const int j    = rem & 3;
            const __nv_bfloat16* g =
                srcs[tile] + (size_t)(rowbase[tile] + r) * K + kb + (j << 3);
            cp_async16(sb + s * STAGE_B + tile * TILE_B + r * TPITCH + (j << 4), g);
        }
    };

    float acc[2][8][4];
#pragma unroll
    for (int mt = 0; mt < 2; mt++)
#pragma unroll
        for (int nt = 0; nt < 8; nt++)
#pragma unroll
            for (int e = 0; e < 4; e++) acc[mt][nt][e] = 0.0f;

    load_stage(0, 0);
    cp_commit();

    // ldmatrix address components (constant per thread)
    const uint32_t a_off = (uint32_t)(warp_m * 32 + (lane & 15)) * TPITCH
                         + ((lane >> 4) << 4);
    const uint32_t b_n   = (uint32_t)(warp_n * 64 + ((lane >> 4) << 3) + (lane & 7));
    const uint32_t b_off = b_n * TPITCH + (((lane >> 3) & 1) << 4);

    for (int i = 0; i < nk; ++i) {
        const int s = i & 1;
        if (i + 1 < nk) {
            load_stage(s ^ 1, (i + 1) << 5);
            cp_commit();
            asm volatile("cp.async.wait_group 1;" ::: "memory");
        } else {
            asm volatile("cp.async.wait_group 0;" ::: "memory");
        }
        __syncthreads();

        const uint32_t st = sb + s * STAGE_B;
#pragma unroll
        for (int k16 = 0; k16 < 2; k16++) {
            const uint32_t kb16 = k16 << 5;      // 32 bytes per k16
            uint32_t a[2][2][4];
            ldsm4(a[0][0], st + 0 * TILE_B + a_off + kb16);            // Ah mt0
            ldsm4(a[0][1], st + 0 * TILE_B + a_off + kb16 + 16 * TPITCH);
            ldsm4(a[1][0], st + 1 * TILE_B + a_off + kb16);            // Al
            ldsm4(a[1][1], st + 1 * TILE_B + a_off + kb16 + 16 * TPITCH);

            uint32_t b[4][4];
#pragma unroll
            for (int q = 0; q < 4; q++)
                ldsm4(b[q], st + 2 * TILE_B + b_off + kb16 + (uint32_t)q * 16 * TPITCH);
#pragma unroll
            for (int mt = 0; mt < 2; mt++)
#pragma unroll
                for (int nt = 0; nt < 8; nt++) {
                    mma16816(acc[mt][nt], a[0][mt], &b[nt >> 1][(nt & 1) * 2]);
                    mma16816(acc[mt][nt], a[1][mt], &b[nt >> 1][(nt & 1) * 2]);
                }
#pragma unroll
            for (int q = 0; q < 4; q++)
                ldsm4(b[q], st + 3 * TILE_B + b_off + kb16 + (uint32_t)q * 16 * TPITCH);
#pragma unroll
            for (int mt = 0; mt < 2; mt++)
#pragma unroll
                for (int nt = 0; nt < 8; nt++)
                    mma16816(acc[mt][nt], a[0][mt], &b[nt >> 1][(nt & 1) * 2]);
        }
        __syncthreads();
    }

    // ---- epilogue ----
    const int g  = lane >> 2;
    const int ti = lane & 3;
#pragma unroll
    for (int mt = 0; mt < 2; mt++) {
        const int row0 = bm + warp_m * 32 + mt * 16 + g;
#pragma unroll
        for (int nt = 0; nt < 8; nt++) {
            const int col = bn + warp_n * 64 + nt * 8 + ti * 2;
            float b0 = bias ? bias[col]     : 0.0f;
            float b1 = bias ? bias[col + 1] : 0.0f;
            float2 v0 = {acc[mt][nt][0] + b0, acc[mt][nt][1] + b1};
            float2 v1 = {acc[mt][nt][2] + b0, acc[mt][nt][3] + b1};
            *(float2*)(C + (size_t)row0 * N + col)       = v0;
            *(float2*)(C + (size_t)(row0 + 8) * N + col) = v1;
        }
    }
}

// ---------------------------------------------------------------------------
// RoPE (mRoPE collapses to slice 0; positions identical across axes)
// ---------------------------------------------------------------------------
__global__ __launch_bounds__(256) void rope_kernel(
    float* __restrict__ Q, float* __restrict__ Kv,
    const float* __restrict__ cosb, const float* __restrict__ sinb)
{
    const int s = blockIdx.x;
    const float* cs = cosb + (size_t)s * DH;
    const float* sn = sinb + (size_t)s * DH;
    const int tid = threadIdx.x;
    for (int i = tid; i < 32 * 64; i += 256) {
        const int head = i >> 6;
        const int d = i & 63;
        float* p = (head < NHQ)
                     ? Q + (size_t)s * HID + head * DH
                     : Kv + (size_t)s * DKV + (head - NHQ) * DH;
        const float c1 = cs[d], c2 = cs[d + 64];
        const float s1 = sn[d], s2 = sn[d + 64];
        const float x1 = p[d], x2 = p[d + 64];
        p[d]      = x1 * c1 - x2 * s1;
        p[d + 64] = x2 * c2 + x1 * s2;
    }
}

// ---------------------------------------------------------------------------
// Causal flash attention, fp32
// ---------------------------------------------------------------------------
#define ATTN_SMEM_FLOATS (8192 + 8192 + 8192 + 64*65 + 64*16 + 192)
#define ATTN_SMEM_BYTES  (ATTN_SMEM_FLOATS * 4)

__global__ __launch_bounds__(256) void attn_kernel(
    const float* __restrict__ Q, const float* __restrict__ K,
    const float* __restrict__ V, float* __restrict__ O)
{
    extern __shared__ __align__(16) float sm[];
    float* QT   = sm;
    float* KT   = sm + 8192;
    float* VS   = sm + 16384;
    float* PS   = sm + 24576;
    float* RED  = sm + 24576 + 4160;
    float* Mrow = RED + 1024;
    float* Lrow = Mrow + 64;
    float* Arow = Lrow + 64;

    const int tid = threadIdx.x;
    const int tx = tid & 15;
    const int ty = tid >> 4;
    const int q0 = blockIdx.x * 64;
    const int h  = blockIdx.y;
    const int kvh = h / N_REP;
    const int r0 = ty * 4;
    const int c0 = tx * 4;

    {
        const int r = tid & 63;
        const int c4b = tid >> 6;
        const float* qg = Q + (size_t)(q0 + r) * HID + h * DH;
#pragma unroll
        for (int it = 0; it < 8; it++) {
            const int d0 = (c4b + it * 4) * 4;
            float4 v = *(const float4*)(qg + d0);
            QT[(d0 + 0) * 64 + r] = v.x;
            QT[(d0 + 1) * 64 + r] = v.y;
            QT[(d0 + 2) * 64 + r] = v.z;
            QT[(d0 + 3) * 64 + r] = v.w;
        }
    }
    if (tid < 64) { Mrow[tid] = -3.0e38f; Lrow[tid] = 0.0f; }

    float oacc[4][8];
#pragma unroll
    for (int i = 0; i < 4; i++)
#pragma unroll
        for (int j = 0; j < 8; j++) oacc[i][j] = 0.0f;

    const float scale = 0.08838834764831845f;
    const int nkt = q0 / 64 + 1;

    for (int kt = 0; kt < nkt; kt++) {
        const int k0 = kt * 64;
        __syncthreads();

        {
            const int r = tid & 63;
            const int c4b = tid >> 6;
            const float* kg = K + (size_t)(k0 + r) * DKV + kvh * DH;
#pragma unroll
            for (int it = 0; it < 8; it++) {
                const int d0 = (c4b + it * 4) * 4;
                float4 v = *(const float4*)(kg + d0);
                KT[(d0 + 0) * 64 + r] = v.x;
                KT[(d0 + 1) * 64 + r] = v.y;
                KT[(d0 + 2) * 64 + r] = v.z;
                KT[(d0 + 3) * 64 + r] = v.w;
            }
        }
        {
            const int vr = tid >> 5;
            const int vc = (tid & 31) * 4;
#pragma unroll
            for (int it = 0; it < 8; it++) {
                const int row = vr + it * 8;
                float4 v = *(const float4*)(V + (size_t)(k0 + row) * DKV + kvh * DH + vc);
                *(float4*)&VS[row * 128 + vc] = v;
            }
        }
        __syncthreads();

        float sacc[4][4];
#pragma unroll
        for (int i = 0; i < 4; i++)
#pragma unroll
            for (int j = 0; j < 4; j++) sacc[i][j] = 0.0f;

#pragma unroll 8
        for (int k = 0; k < 128; k++) {
            float4 qa = *(const float4*)&QT[k * 64 + r0];
            float4 ka = *(const float4*)&KT[k * 64 + c0];
            float qv[4] = {qa.x, qa.y, qa.z, qa.w};
            float kv[4] = {ka.x, ka.y, ka.z, ka.w};
#pragma unroll
            for (int i = 0; i < 4; i++)
#pragma unroll
                for (int j = 0; j < 4; j++)
                    sacc[i][j] += qv[i] * kv[j];
        }

#pragma unroll
        for (int i = 0; i < 4; i++) {
            float mx = -3.0e38f;
#pragma unroll
            for (int j = 0; j < 4; j++) {
                float s = sacc[i][j] * scale;
                if (k0 + c0 + j > q0 + r0 + i) s = -3.0e38f;
                sacc[i][j] = s;
                mx = fmaxf(mx, s);
            }
            RED[(r0 + i) * 16 + tx] = mx;
        }
        __syncthreads();
        if (tid < 64) {
            float mt = RED[tid * 16];
#pragma unroll
            for (int j = 1; j < 16; j++) mt = fmaxf(mt, RED[tid * 16 + j]);
            const float mold = Mrow[tid];
            const float mnew = fmaxf(mold, mt);
            Arow[tid] = __expf(mold - mnew);
            Mrow[tid] = mnew;
        }
        __syncthreads();

#pragma unroll
        for (int i = 0; i < 4; i++) {
            const float mr = Mrow[r0 + i];
            float rs = 0.0f;
#pragma unroll
            for (int j = 0; j < 4; j++) {
                const float p = __expf(sacc[i][j] - mr);
                PS[(r0 + i) * 65 + c0 + j] = p;
                rs += p;
            }
            RED[(r0 + i) * 16 + tx] = rs;
        }
        __syncthreads();
        if (tid < 64) {
            float s = 0.0f;
#pragma unroll
            for (int j = 0; j < 16; j++) s += RED[tid * 16 + j];
            Lrow[tid] = Lrow[tid] * Arow[tid] + s;
        }

#pragma unroll
        for (int i = 0; i < 4; i++) {
            const float al = Arow[r0 + i];
#pragma unroll
            for (int j = 0; j < 8; j++) oacc[i][j] *= al;
        }

#pragma unroll 4
        for (int kk = 0; kk < 64; kk++) {
            float p[4];
#pragma unroll
            for (int i = 0; i < 4; i++) p[i] = PS[(r0 + i) * 65 + kk];
            float4 v0 = *(const float4*)&VS[kk * 128 + tx * 8];
            float4 v1 = *(const float4*)&VS[kk * 128 + tx * 8 + 4];
            float v[8] = {v0.x, v0.y, v0.z, v0.w, v1.x, v1.y, v1.z, v1.w};
#pragma unroll
            for (int i = 0; i < 4; i++)
#pragma unroll
                for (int j = 0; j < 8; j++)
                    oacc[i][j] += p[i] * v[j];
        }
    }

    __syncthreads();
#pragma unroll
    for (int i = 0; i < 4; i++) {
        const float inv = 1.0f / Lrow[r0 + i];
        float* og = O + (size_t)(q0 + r0 + i) * HID + h * DH + tx * 8;
        float4 o0, o1;
        o0.x = oacc[i][0] * inv; o0.y = oacc[i][1] * inv;
        o0.z = oacc[i][2] * inv; o0.w = oacc[i][3] * inv;
        o1.x = oacc[i][4] * inv; o1.y = oacc[i][5] * inv;
        o1.z = oacc[i][6] * inv; o1.w = oacc[i][7] * inv;
        *(float4*)(og) = o0;
        *(float4*)(og + 4) = o1;
    }
}

// ---------------------------------------------------------------------------
// Launch
// ---------------------------------------------------------------------------
static void run_split(const float* x, __nv_bfloat16* h, __nv_bfloat16* l, int n) {
    int n4 = n / 4;
    split_bf16<<<(n4 + 255) / 256, 256>>>(x, h, l, n4);
}

extern "C" void kernel_launch(void* const* d_in, const int* in_sizes, int n_in,
                              void* d_out, int out_size)
{
    const float* hs   = (const float*)d_in[0];
    const float* Wq   = (const float*)d_in[1];
    const float* bq   = (const float*)d_in[2];
    const float* Wk   = (const float*)d_in[3];
    const float* bk   = (const float*)d_in[4];
    const float* Wv   = (const float*)d_in[5];
    const float* bv   = (const float*)d_in[6];
    const float* Wo   = (const float*)d_in[7];
    const float* cosb = (const float*)d_in[8];
    const float* sinb = (const float*)d_in[9];
    float* out = (float*)d_out;

    float *Qp, *Kp, *Vp, *AOp;
    cudaGetSymbolAddress((void**)&Qp, g_Q);
    cudaGetSymbolAddress((void**)&Kp, g_K);
    cudaGetSymbolAddress((void**)&Vp, g_V);
    cudaGetSymbolAddress((void**)&AOp, g_AO);

    __nv_bfloat16 *hsh, *hsl, *aoh, *aol, *wqh, *wql, *wkh, *wkl, *wvh, *wvl, *woh, *wol;
    cudaGetSymbolAddress((void**)&hsh, g_hs_h); cudaGetSymbolAddress((void**)&hsl, g_hs_l);
    cudaGetSymbolAddress((void**)&aoh, g_ao_h); cudaGetSymbolAddress((void**)&aol, g_ao_l);
    cudaGetSymbolAddress((void**)&wqh, g_wq_h); cudaGetSymbolAddress((void**)&wql, g_wq_l);
    cudaGetSymbolAddress((void**)&wkh, g_wk_h); cudaGetSymbolAddress((void**)&wkl, g_wk_l);
    cudaGetSymbolAddress((void**)&wvh, g_wv_h); cudaGetSymbolAddress((void**)&wvl, g_wv_l);
    cudaGetSymbolAddress((void**)&woh, g_wo_h); cudaGetSymbolAddress((void**)&wol, g_wo_l);

    cudaFuncSetAttribute(attn_kernel, cudaFuncAttributeMaxDynamicSharedMemorySize,
                         ATTN_SMEM_BYTES);
    cudaFuncSetAttribute(gemm_bf16x3, cudaFuncAttributeMaxDynamicSharedMemorySize,
                         GEMM_SMEM_BYTES);

    // fp32 -> bf16 hi/lo splits
    run_split(hs, hsh, hsl, S_LEN * HID);
    run_split(Wq, wqh, wql, HID * HID);
    run_split(Wk, wkh, wkl, DKV * HID);
    run_split(Wv, wvh, wvl, DKV * HID);
    run_split(Wo, woh, wol, HID * HID);

    // projections on tensor cores (HMMA)
    gemm_bf16x3<<<dim3(HID / 128, S_LEN / 128), 256, GEMM_SMEM_BYTES>>>(
        hsh, hsl, wqh, wql, bq, Qp, S_LEN, HID, HID);
    gemm_bf16x3<<<dim3(DKV / 128, S_LEN / 128), 256, GEMM_SMEM_BYTES>>>(
        hsh, hsl, wkh, wkl, bk, Kp, S_LEN, DKV, HID);
    gemm_bf16x3<<<dim3(DKV / 128, S_LEN / 128), 256, GEMM_SMEM_BYTES>>>(
        hsh, hsl, wvh, wvl, bv, Vp, S_LEN, DKV, HID);

    rope_kernel<<<S_LEN, 256>>>(Qp, Kp, cosb, sinb);

    attn_kernel<<<dim3(S_LEN / 64, NHQ), 256, ATTN_SMEM_BYTES>>>(Qp, Kp, Vp, AOp);

    run_split(AOp, aoh, aol, S_LEN * HID);
    gemm_bf16x3<<<dim3(HID / 128, S_LEN / 128), 256, GEMM_SMEM_BYTES>>>(
        aoh, aol, woh, wol, nullptr, out, S_LEN, HID, HID);
}

// round 5
// speedup vs baseline: 2.1593x; 1.0800x over previous
#include <cuda_runtime.h>
#include <cuda_bf16.h>
#include <stdint.h>
#include <math.h>

#define S_LEN 2048
#define HID   3584
#define NHQ   28
#define NKV   4
#define DH    128
#define DKV   (NKV * DH)   // 512
#define N_REP (NHQ / NKV)  // 7

// ---------------- scratch (__device__ globals; no allocs allowed) ----------
__device__ float g_Q[S_LEN * HID];
__device__ float g_K[S_LEN * DKV];
__device__ float g_V[S_LEN * DKV];
__device__ float g_AO[S_LEN * HID];

__device__ __nv_bfloat16 g_hs_h[S_LEN * HID],  g_hs_l[S_LEN * HID];
__device__ __nv_bfloat16 g_ao_h[S_LEN * HID],  g_ao_l[S_LEN * HID];
__device__ __nv_bfloat16 g_wq_h[HID * HID],    g_wq_l[HID * HID];
__device__ __nv_bfloat16 g_wo_h[HID * HID],    g_wo_l[HID * HID];
__device__ __nv_bfloat16 g_wk_h[DKV * HID],    g_wk_l[DKV * HID];
__device__ __nv_bfloat16 g_wv_h[DKV * HID],    g_wv_l[DKV * HID];

// post-RoPE bf16 splits for attention
__device__ __nv_bfloat16 g_q_h[S_LEN * HID],  g_q_l[S_LEN * HID];
__device__ __nv_bfloat16 g_k_h[S_LEN * DKV],  g_k_l[S_LEN * DKV];
__device__ __nv_bfloat16 g_v_h[S_LEN * DKV],  g_v_l[S_LEN * DKV];

// ---------------- PTX helpers ---------------------------------------------
__device__ __forceinline__ uint32_t smem_u32(const void* p) {
    uint32_t a;
    asm("{ .reg .u64 t; cvta.to.shared.u64 t, %1; cvt.u32.u64 %0, t; }"
        : "=r"(a) : "l"(p));
    return a;
}
__device__ __forceinline__ void cp_async16(uint32_t dst, const void* src) {
    asm volatile("cp.async.cg.shared.global [%0], [%1], 16;\n"
                 :: "r"(dst), "l"(src) : "memory");
}
__device__ __forceinline__ void cp_commit() {
    asm volatile("cp.async.commit_group;" ::: "memory");
}
__device__ __forceinline__ void ldsm4(uint32_t* r, uint32_t addr) {
    asm volatile("ldmatrix.sync.aligned.m8n8.x4.shared.b16 {%0,%1,%2,%3}, [%4];\n"
                 : "=r"(r[0]), "=r"(r[1]), "=r"(r[2]), "=r"(r[3]) : "r"(addr));
}
__device__ __forceinline__ void ldsm4t(uint32_t* r, uint32_t addr) {
    asm volatile("ldmatrix.sync.aligned.m8n8.x4.trans.shared.b16 {%0,%1,%2,%3}, [%4];\n"
                 : "=r"(r[0]), "=r"(r[1]), "=r"(r[2]), "=r"(r[3]) : "r"(addr));
}
__device__ __forceinline__ void mma16816(float* c, const uint32_t* a,
                                         const uint32_t* b) {
    asm volatile(
        "mma.sync.aligned.m16n8k16.row.col.f32.bf16.bf16.f32 "
        "{%0,%1,%2,%3}, {%4,%5,%6,%7}, {%8,%9}, {%0,%1,%2,%3};\n"
        : "+f"(c[0]), "+f"(c[1]), "+f"(c[2]), "+f"(c[3])
        : "r"(a[0]), "r"(a[1]), "r"(a[2]), "r"(a[3]), "r"(b[0]), "r"(b[1]));
}
__device__ __forceinline__ float ex2f(float x) {
    float y;
    asm("ex2.approx.ftz.f32 %0, %1;" : "=f"(y) : "f"(x));
    return y;
}
__device__ __forceinline__ uint32_t packbf(float a, float b) {
    __nv_bfloat162 t = __floats2bfloat162_rn(a, b);
    return *reinterpret_cast<uint32_t*>(&t);
}

// ---------------------------------------------------------------------------
// fp32 -> bf16 hi/lo split (elementwise)
// ---------------------------------------------------------------------------
__global__ __launch_bounds__(256) void split_bf16(
    const float* __restrict__ x, __nv_bfloat16* __restrict__ h,
    __nv_bfloat16* __restrict__ l, int n4)
{
    int i = blockIdx.x * blockDim.x + threadIdx.x;
    if (i >= n4) return;
    float4 v = ((const float4*)x)[i];
    float vv[4] = {v.x, v.y, v.z, v.w};
    __nv_bfloat16 hh[4], ll[4];
#pragma unroll
    for (int j = 0; j < 4; j++) {
        hh[j] = __float2bfloat16(vv[j]);
        ll[j] = __float2bfloat16(vv[j] - __bfloat162float(hh[j]));
    }
    __nv_bfloat162* hp = (__nv_bfloat162*)(h + i * 4);
    __nv_bfloat162* lp = (__nv_bfloat162*)(l + i * 4);
    hp[0] = __nv_bfloat162(hh[0], hh[1]); hp[1] = __nv_bfloat162(hh[2], hh[3]);
    lp[0] = __nv_bfloat162(ll[0], ll[1]); lp[1] = __nv_bfloat162(ll[2], ll[3]);
}

// ---------------------------------------------------------------------------
// bf16x3 HMMA GEMM: C[M,N] = A[M,K] @ B[N,K]^T + bias  (unchanged, proven)
// ---------------------------------------------------------------------------
#define TPITCH 80
#define TILE_B 10240
#define STAGE_B 40960
#define GEMM_SMEM_BYTES (2 * STAGE_B)

__global__ __launch_bounds__(256, 2) void gemm_bf16x3(
    const __nv_bfloat16* __restrict__ Ah, const __nv_bfloat16* __restrict__ Al,
    const __nv_bfloat16* __restrict__ Bh, const __nv_bfloat16* __restrict__ Bl,
    const float* __restrict__ bias, float* __restrict__ C,
    int M, int N, int K)
{
    extern __shared__ __align__(128) char smem[];
    const uint32_t sb = smem_u32(smem);
    const int tid  = threadIdx.x;
    const int wid  = tid >> 5;
    const int lane = tid & 31;
    const int warp_m = wid & 3;
    const int warp_n = wid >> 2;
    const int bm = blockIdx.y * 128;
    const int bn = blockIdx.x * 128;
    const int nk = K >> 5;

    const __nv_bfloat16* srcs[4] = {Ah, Al, Bh, Bl};
    const int rowbase[4] = {bm, bm, bn, bn};

    auto load_stage = [&](int s, int kb) {
#pragma unroll
        for (int i = 0; i < 8; ++i) {
            const int c    = (i << 8) + tid;
            const int tile = c >> 9;
            const int rem  = c & 511;
            const int r    = rem >> 2;
            const int j    = rem & 3;
            const __nv_bfloat16* g =
                srcs[tile] + (size_t)(rowbase[tile] + r) * K + kb + (j << 3);
            cp_async16(sb + s * STAGE_B + tile * TILE_B + r * TPITCH + (j << 4), g);
        }
    };

    float acc[2][8][4];
#pragma unroll
    for (int mt = 0; mt < 2; mt++)
#pragma unroll
        for (int nt = 0; nt < 8; nt++)
#pragma unroll
            for (int e = 0; e < 4; e++) acc[mt][nt][e] = 0.0f;

    load_stage(0, 0);
    cp_commit();

    const uint32_t a_off = (uint32_t)(warp_m * 32 + (lane & 15)) * TPITCH
                         + ((lane >> 4) << 4);
    const uint32_t b_n   = (uint32_t)(warp_n * 64 + ((lane >> 4) << 3) + (lane & 7));
    const uint32_t b_off = b_n * TPITCH + (((lane >> 3) & 1) << 4);

    for (int i = 0; i < nk; ++i) {
        const int s = i & 1;
        if (i + 1 < nk) {
            load_stage(s ^ 1, (i + 1) << 5);
            cp_commit();
            asm volatile("cp.async.wait_group 1;" ::: "memory");
        } else {
            asm volatile("cp.async.wait_group 0;" ::: "memory");
        }
        __syncthreads();

        const uint32_t st = sb + s * STAGE_B;
#pragma unroll
        for (int k16 = 0; k16 < 2; k16++) {
            const uint32_t kb16 = k16 << 5;
            uint32_t a[2][2][4];
            ldsm4(a[0][0], st + 0 * TILE_B + a_off + kb16);
            ldsm4(a[0][1], st + 0 * TILE_B + a_off + kb16 + 16 * TPITCH);
            ldsm4(a[1][0], st + 1 * TILE_B + a_off + kb16);
            ldsm4(a[1][1], st + 1 * TILE_B + a_off + kb16 + 16 * TPITCH);

            uint32_t b[4][4];
#pragma unroll
            for (int q = 0; q < 4; q++)
                ldsm4(b[q], st + 2 * TILE_B + b_off + kb16 + (uint32_t)q * 16 * TPITCH);
#pragma unroll
            for (int mt = 0; mt < 2; mt++)
#pragma unroll
                for (int nt = 0; nt < 8; nt++) {
                    mma16816(acc[mt][nt], a[0][mt], &b[nt >> 1][(nt & 1) * 2]);
                    mma16816(acc[mt][nt], a[1][mt], &b[nt >> 1][(nt & 1) * 2]);
                }
#pragma unroll
            for (int q = 0; q < 4; q++)
                ldsm4(b[q], st + 3 * TILE_B + b_off + kb16 + (uint32_t)q * 16 * TPITCH);
#pragma unroll
            for (int mt = 0; mt < 2; mt++)
#pragma unroll
                for (int nt = 0; nt < 8; nt++)
                    mma16816(acc[mt][nt], a[0][mt], &b[nt >> 1][(nt & 1) * 2]);
        }
        __syncthreads();
    }

    const int g  = lane >> 2;
    const int ti = lane & 3;
#pragma unroll
    for (int mt = 0; mt < 2; mt++) {
        const int row0 = bm + warp_m * 32 + mt * 16 + g;
#pragma unroll
        for (int nt = 0; nt < 8; nt++) {
            const int col = bn + warp_n * 64 + nt * 8 + ti * 2;
            float b0 = bias ? bias[col]     : 0.0f;
            float b1 = bias ? bias[col + 1] : 0.0f;
            float2 v0 = {acc[mt][nt][0] + b0, acc[mt][nt][1] + b1};
            float2 v1 = {acc[mt][nt][2] + b0, acc[mt][nt][3] + b1};
            *(float2*)(C + (size_t)row0 * N + col)       = v0;
            *(float2*)(C + (size_t)(row0 + 8) * N + col) = v1;
        }
    }
}

// ---------------------------------------------------------------------------
// RoPE (mRoPE collapses to slice 0; positions identical across axes)
// ---------------------------------------------------------------------------
__global__ __launch_bounds__(256) void rope_kernel(
    float* __restrict__ Q, float* __restrict__ Kv,
    const float* __restrict__ cosb, const float* __restrict__ sinb)
{
    const int s = blockIdx.x;
    const float* cs = cosb + (size_t)s * DH;
    const float* sn = sinb + (size_t)s * DH;
    const int tid = threadIdx.x;
    for (int i = tid; i < 32 * 64; i += 256) {
        const int head = i >> 6;
        const int d = i & 63;
        float* p = (head < NHQ)
                     ? Q + (size_t)s * HID + head * DH
                     : Kv + (size_t)s * DKV + (head - NHQ) * DH;
        const float c1 = cs[d], c2 = cs[d + 64];
        const float s1 = sn[d], s2 = sn[d + 64];
        const float x1 = p[d], x2 = p[d + 64];
        p[d]      = x1 * c1 - x2 * s1;
        p[d + 64] = x2 * c2 + x1 * s2;
    }
}

// ---------------------------------------------------------------------------
// HMMA bf16x3 causal flash attention.
// Grid (16, 28), 256 thr (8 warps). CTA: 128 queries x one head.
// smem: Qh/Ql resident (128x128 bf16, pitch 272B), K/V hi/lo double-buffered.
// ---------------------------------------------------------------------------
#define APITCH 272
#define QHALF  34816               // 128*272
#define KVSTG  69632               // 4 * 64*272
#define ATTN_SMEM_BYTES (QHALF * 2 + KVSTG * 2)   // 208896

__global__ __launch_bounds__(256, 1) void attn_hmma(
    const __nv_bfloat16* __restrict__ qh_, const __nv_bfloat16* __restrict__ ql_,
    const __nv_bfloat16* __restrict__ kh_, const __nv_bfloat16* __restrict__ kl_,
    const __nv_bfloat16* __restrict__ vh_, const __nv_bfloat16* __restrict__ vl_,
    float* __restrict__ O)
{
    extern __shared__ __align__(128) char smem[];
    const uint32_t sb = smem_u32(smem);
    const int tid  = threadIdx.x;
    const int wid  = tid >> 5;
    const int lane = tid & 31;
    const int qb = blockIdx.x;
    const int h  = blockIdx.y;
    const int kvh = h / N_REP;
    const int q0 = qb * 128;
    const int m0 = wid * 16;
    const int nkt = 2 * qb + 2;
    const float kscale = 0.08838834764831845f * 1.4426950408889634f;

    // ---- Q tiles (hi, lo) ----
#pragma unroll
    for (int it = 0; it < 16; ++it) {
        int idx = it * 256 + tid;
        int half = idx >> 11, rem = idx & 2047;
        int r = rem >> 4, c = rem & 15;
        const __nv_bfloat16* src =
            (half ? ql_ : qh_) + (size_t)(q0 + r) * HID + h * DH + c * 8;
        cp_async16(sb + half * QHALF + r * APITCH + c * 16, src);
    }
    cp_commit();

    auto load_kv = [&](int s, int kt) {
        const int k0 = kt * 64;
        const __nv_bfloat16* srcs[4] = {kh_, kl_, vh_, vl_};
#pragma unroll
        for (int it = 0; it < 16; ++it) {
            int idx = it * 256 + tid;
            int tz = idx >> 10, rem = idx & 1023;
            int r = rem >> 4, c = rem & 15;
            const __nv_bfloat16* src =
                srcs[tz] + (size_t)(k0 + r) * DKV + kvh * DH + c * 8;
            cp_async16(sb + 2 * QHALF + s * KVSTG + tz * 17408 + r * APITCH + c * 16,
                       src);
        }
        cp_commit();
    };
    load_kv(0, 0);

    float oacc[16][4];
#pragma unroll
    for (int f = 0; f < 16; f++)
#pragma unroll
        for (int e = 0; e < 4; e++) oacc[f][e] = 0.0f;
    float m_lo = -1e30f, m_hi = -1e30f, l_lo = 0.0f, l_hi = 0.0f;

    const uint32_t a_q   = sb + (uint32_t)(m0 + (lane & 15)) * APITCH
                         + ((lane >> 4) << 4);
    const uint32_t bkrow = ((lane >> 4) << 3) + (lane & 7);
    const uint32_t bkoff = (((lane >> 3) & 1) << 4);
    const uint32_t vrow  = (lane & 15);
    const uint32_t vcoff = ((lane >> 4) << 4);
    const int row_off  = lane >> 2;
    const int col_base = (lane & 3) * 2;
    const int row_lo_g = q0 + m0 + row_off;
    const int row_hi_g = row_lo_g + 8;

    for (int kt = 0; kt < nkt; ++kt) {
        const int s  = kt & 1;
        const int k0 = kt * 64;
        if (kt + 1 < nkt) {
            load_kv(s ^ 1, kt + 1);
            asm volatile("cp.async.wait_group 1;" ::: "memory");
        } else {
            asm volatile("cp.async.wait_group 0;" ::: "memory");
        }
        __syncthreads();

        const uint32_t kvb = sb + 2 * QHALF + s * KVSTG;
        const uint32_t khb = kvb, klb = kvb + 17408;
        const uint32_t vhb = kvb + 34816, vlb = kvb + 52224;

        // ---- S = Q K^T (bf16x3) ----
        float sacc[8][4];
#pragma unroll
        for (int f = 0; f < 8; f++)
#pragma unroll
            for (int e = 0; e < 4; e++) sacc[f][e] = 0.0f;

#pragma unroll
        for (int k16 = 0; k16 < 8; k16++) {
            uint32_t ah[4], al[4], bt[4];
            ldsm4(ah, a_q + k16 * 32);
            ldsm4(al, a_q + QHALF + k16 * 32);
#pragma unroll
            for (int g = 0; g < 4; g++) {
                const uint32_t baddr =
                    (uint32_t)(16 * g + bkrow) * APITCH + bkoff + k16 * 32;
                ldsm4(bt, khb + baddr);
                mma16816(sacc[2 * g],     ah, bt);
                mma16816(sacc[2 * g + 1], ah, bt + 2);
                mma16816(sacc[2 * g],     al, bt);
                mma16816(sacc[2 * g + 1], al, bt + 2);
                ldsm4(bt, klb + baddr);
                mma16816(sacc[2 * g],     ah, bt);
                mma16816(sacc[2 * g + 1], ah, bt + 2);
            }
        }

        // ---- scale + mask + online softmax ----
        const bool flag = (k0 + 63 > q0);
        float tmx_lo = -1e30f, tmx_hi = -1e30f;
#pragma unroll
        for (int f = 0; f < 8; f++) {
            const int c0g = k0 + 8 * f + col_base;
#pragma unroll
            for (int j = 0; j < 2; j++) {
                float x = sacc[f][j] * kscale;
                if (flag && (c0g + j > row_lo_g)) x = -1e30f;
                sacc[f][j] = x;
                tmx_lo = fmaxf(tmx_lo, x);
                float y = sacc[f][j + 2] * kscale;
                if (flag && (c0g + j > row_hi_g)) y = -1e30f;
                sacc[f][j + 2] = y;
                tmx_hi = fmaxf(tmx_hi, y);
            }
        }
        tmx_lo = fmaxf(tmx_lo, __shfl_xor_sync(0xffffffffu, tmx_lo, 1));
        tmx_lo = fmaxf(tmx_lo, __shfl_xor_sync(0xffffffffu, tmx_lo, 2));
        tmx_hi = fmaxf(tmx_hi, __shfl_xor_sync(0xffffffffu, tmx_hi, 1));
        tmx_hi = fmaxf(tmx_hi, __shfl_xor_sync(0xffffffffu, tmx_hi, 2));

        const float mn_lo = fmaxf(m_lo, tmx_lo);
        const float mn_hi = fmaxf(m_hi, tmx_hi);
        const float al_lo = ex2f(m_lo - mn_lo);
        const float al_hi = ex2f(m_hi - mn_hi);
        m_lo = mn_lo; m_hi = mn_hi;

        uint32_t Ph[16], Pl[16];
        float ps_lo = 0.0f, ps_hi = 0.0f;
#pragma unroll
        for (int f = 0; f < 8; f++) {
            float p0 = ex2f(sacc[f][0] - m_lo);
            float p1 = ex2f(sacc[f][1] - m_lo);
            float p2 = ex2f(sacc[f][2] - m_hi);
            float p3 = ex2f(sacc[f][3] - m_hi);
            ps_lo += p0 + p1; ps_hi += p2 + p3;
            float h0 = __bfloat162float(__float2bfloat16(p0));
            float h1 = __bfloat162float(__float2bfloat16(p1));
            float h2 = __bfloat162float(__float2bfloat16(p2));
            float h3 = __bfloat162float(__float2bfloat16(p3));
            const int c  = f >> 1;
            const int rb = (f & 1) * 2;
            Ph[c * 4 + rb]     = packbf(h0, h1);
            Ph[c * 4 + rb + 1] = packbf(h2, h3);
            Pl[c * 4 + rb]     = packbf(p0 - h0, p1 - h1);
            Pl[c * 4 + rb + 1] = packbf(p2 - h2, p3 - h3);
        }
        ps_lo += __shfl_xor_sync(0xffffffffu, ps_lo, 1);
        ps_lo += __shfl_xor_sync(0xffffffffu, ps_lo, 2);
        ps_hi += __shfl_xor_sync(0xffffffffu, ps_hi, 1);
        ps_hi += __shfl_xor_sync(0xffffffffu, ps_hi, 2);
        l_lo = l_lo * al_lo + ps_lo;
        l_hi = l_hi * al_hi + ps_hi;

#pragma unroll
        for (int f = 0; f < 16; f++) {
            oacc[f][0] *= al_lo; oacc[f][1] *= al_lo;
            oacc[f][2] *= al_hi; oacc[f][3] *= al_hi;
        }

        // ---- O += P V (bf16x3), V via ldmatrix.trans ----
#pragma unroll
        for (int c = 0; c < 4; c++) {
#pragma unroll
            for (int g = 0; g < 8; g++) {
                const uint32_t baddr =
                    (uint32_t)(16 * c + vrow) * APITCH + 32 * g + vcoff;
                uint32_t bt[4];
                ldsm4t(bt, vhb + baddr);
                mma16816(oacc[2 * g],     &Ph[c * 4], bt);
                mma16816(oacc[2 * g + 1], &Ph[c * 4], bt + 2);
                mma16816(oacc[2 * g],     &Pl[c * 4], bt);
                mma16816(oacc[2 * g + 1], &Pl[c * 4], bt + 2);
                ldsm4t(bt, vlb + baddr);
                mma16816(oacc[2 * g],     &Ph[c * 4], bt);
                mma16816(oacc[2 * g + 1], &Ph[c * 4], bt + 2);
            }
        }
        __syncthreads();
    }

    // ---- normalize + store ----
    const float inv_lo = 1.0f / l_lo;
    const float inv_hi = 1.0f / l_hi;
#pragma unroll
    for (int f = 0; f < 16; f++) {
        const int col = 8 * f + col_base;
        float2 v0 = {oacc[f][0] * inv_lo, oacc[f][1] * inv_lo};
        float2 v1 = {oacc[f][2] * inv_hi, oacc[f][3] * inv_hi};
        *(float2*)(O + (size_t)row_lo_g * HID + h * DH + col) = v0;
        *(float2*)(O + (size_t)row_hi_g * HID + h * DH + col) = v1;
    }
}

// ---------------------------------------------------------------------------
// Launch
// ---------------------------------------------------------------------------
static void run_split(const float* x, __nv_bfloat16* h, __nv_bfloat16* l, int n) {
    int n4 = n / 4;
    split_bf16<<<(n4 + 255) / 256, 256>>>(x, h, l, n4);
}

extern "C" void kernel_launch(void* const* d_in, const int* in_sizes, int n_in,
                              void* d_out, int out_size)
{
    const float* hs   = (const float*)d_in[0];
    const float* Wq   = (const float*)d_in[1];
    const float* bq   = (const float*)d_in[2];
    const float* Wk   = (const float*)d_in[3];
    const float* bk   = (const float*)d_in[4];
    const float* Wv   = (const float*)d_in[5];
    const float* bv   = (const float*)d_in[6];
    const float* Wo   = (const float*)d_in[7];
    const float* cosb = (const float*)d_in[8];
    const float* sinb = (const float*)d_in[9];
    float* out = (float*)d_out;

    float *Qp, *Kp, *Vp, *AOp;
    cudaGetSymbolAddress((void**)&Qp, g_Q);
    cudaGetSymbolAddress((void**)&Kp, g_K);
    cudaGetSymbolAddress((void**)&Vp, g_V);
    cudaGetSymbolAddress((void**)&AOp, g_AO);

    __nv_bfloat16 *hsh, *hsl, *aoh, *aol, *wqh, *wql, *wkh, *wkl, *wvh, *wvl, *woh, *wol;
    __nv_bfloat16 *qh, *ql, *kh, *kl, *vh, *vl;
    cudaGetSymbolAddress((void**)&hsh, g_hs_h); cudaGetSymbolAddress((void**)&hsl, g_hs_l);
    cudaGetSymbolAddress((void**)&aoh, g_ao_h); cudaGetSymbolAddress((void**)&aol, g_ao_l);
    cudaGetSymbolAddress((void**)&wqh, g_wq_h); cudaGetSymbolAddress((void**)&wql, g_wq_l);
    cudaGetSymbolAddress((void**)&wkh, g_wk_h); cudaGetSymbolAddress((void**)&wkl, g_wk_l);
    cudaGetSymbolAddress((void**)&wvh, g_wv_h); cudaGetSymbolAddress((void**)&wvl, g_wv_l);
    cudaGetSymbolAddress((void**)&woh, g_wo_h); cudaGetSymbolAddress((void**)&wol, g_wo_l);
    cudaGetSymbolAddress((void**)&qh, g_q_h);   cudaGetSymbolAddress((void**)&ql, g_q_l);
    cudaGetSymbolAddress((void**)&kh, g_k_h);   cudaGetSymbolAddress((void**)&kl, g_k_l);
    cudaGetSymbolAddress((void**)&vh, g_v_h);   cudaGetSymbolAddress((void**)&vl, g_v_l);

    cudaFuncSetAttribute(gemm_bf16x3, cudaFuncAttributeMaxDynamicSharedMemorySize,
                         GEMM_SMEM_BYTES);
    cudaFuncSetAttribute(attn_hmma, cudaFuncAttributeMaxDynamicSharedMemorySize,
                         ATTN_SMEM_BYTES);

    // fp32 -> bf16 hi/lo splits (inputs + weights)
    run_split(hs, hsh, hsl, S_LEN * HID);
    run_split(Wq, wqh, wql, HID * HID);
    run_split(Wk, wkh, wkl, DKV * HID);
    run_split(Wv, wvh, wvl, DKV * HID);
    run_split(Wo, woh, wol, HID * HID);

    // projections (HMMA bf16x3)
    gemm_bf16x3<<<dim3(HID / 128, S_LEN / 128), 256, GEMM_SMEM_BYTES>>>(
        hsh, hsl, wqh, wql, bq, Qp, S_LEN, HID, HID);
    gemm_bf16x3<<<dim3(DKV / 128, S_LEN / 128), 256, GEMM_SMEM_BYTES>>>(
        hsh, hsl, wkh, wkl, bk, Kp, S_LEN, DKV, HID);
    gemm_bf16x3<<<dim3(DKV / 128, S_LEN / 128), 256, GEMM_SMEM_BYTES>>>(
        hsh, hsl, wvh, wvl, bv, Vp, S_LEN, DKV, HID);

    rope_kernel<<<S_LEN, 256>>>(Qp, Kp, cosb, sinb);

    // post-RoPE hi/lo splits for attention operands
    run_split(Qp, qh, ql, S_LEN * HID);
    run_split(Kp, kh, kl, S_LEN * DKV);
    run_split(Vp, vh, vl, S_LEN * DKV);

    attn_hmma<<<dim3(S_LEN / 128, NHQ), 256, ATTN_SMEM_BYTES>>>(
        qh, ql, kh, kl, vh, vl, AOp);

    run_split(AOp, aoh, aol, S_LEN * HID);
    gemm_bf16x3<<<dim3(HID / 128, S_LEN / 128), 256, GEMM_SMEM_BYTES>>>(
        aoh, aol, woh, wol, nullptr, out, S_LEN, HID, HID);
}

// round 7
// speedup vs baseline: 3.7723x; 1.7470x over previous
#include <cuda_runtime.h>
#include <cuda_bf16.h>
#include <stdint.h>
#include <math.h>

#define S_LEN 2048
#define HID   3584
#define NHQ   28
#define NKV   4
#define DH    128
#define DKV   (NKV * DH)   // 512
#define N_REP (NHQ / NKV)  // 7

// ---------------- scratch (__device__ globals; no allocs allowed) ----------
__device__ float g_Q[S_LEN * HID];     // pre-RoPE Q (fp32)
__device__ float g_K[S_LEN * DKV];     // pre-RoPE K (fp32)

__device__ __nv_bfloat16 g_hs_h[S_LEN * HID],  g_hs_l[S_LEN * HID];
__device__ __nv_bfloat16 g_ao_h[S_LEN * HID],  g_ao_l[S_LEN * HID];
__device__ __nv_bfloat16 g_wq_h[HID * HID],    g_wq_l[HID * HID];
__device__ __nv_bfloat16 g_wo_h[HID * HID],    g_wo_l[HID * HID];
__device__ __nv_bfloat16 g_wk_h[DKV * HID],    g_wk_l[DKV * HID];
__device__ __nv_bfloat16 g_wv_h[DKV * HID],    g_wv_l[DKV * HID];

// post-RoPE bf16 splits for attention
__device__ __nv_bfloat16 g_q_h[S_LEN * HID],  g_q_l[S_LEN * HID];
__device__ __nv_bfloat16 g_k_h[S_LEN * DKV],  g_k_l[S_LEN * DKV];
__device__ __nv_bfloat16 g_v_h[S_LEN * DKV],  g_v_l[S_LEN * DKV];

// ---------------- PTX helpers ---------------------------------------------
__device__ __forceinline__ uint32_t smem_u32(const void* p) {
    uint32_t a;
    asm("{ .reg .u64 t; cvta.to.shared.u64 t, %1; cvt.u32.u64 %0, t; }"
        : "=r"(a) : "l"(p));
    return a;
}
__device__ __forceinline__ void cp_async16(uint32_t dst, const void* src) {
    asm volatile("cp.async.cg.shared.global [%0], [%1], 16;\n"
                 :: "r"(dst), "l"(src) : "memory");
}
__device__ __forceinline__ void cp_commit() {
    asm volatile("cp.async.commit_group;" ::: "memory");
}
__device__ __forceinline__ void ldsm4(uint32_t* r, uint32_t addr) {
    asm volatile("ldmatrix.sync.aligned.m8n8.x4.shared.b16 {%0,%1,%2,%3}, [%4];\n"
                 : "=r"(r[0]), "=r"(r[1]), "=r"(r[2]), "=r"(r[3]) : "r"(addr));
}
__device__ __forceinline__ void ldsm4t(uint32_t* r, uint32_t addr) {
    asm volatile("ldmatrix.sync.aligned.m8n8.x4.trans.shared.b16 {%0,%1,%2,%3}, [%4];\n"
                 : "=r"(r[0]), "=r"(r[1]), "=r"(r[2]), "=r"(r[3]) : "r"(addr));
}
__device__ __forceinline__ void mma16816(float* c, const uint32_t* a,
                                         const uint32_t* b) {
    asm volatile(
        "mma.sync.aligned.m16n8k16.row.col.f32.bf16.bf16.f32 "
        "{%0,%1,%2,%3}, {%4,%5,%6,%7}, {%8,%9}, {%0,%1,%2,%3};\n"
        : "+f"(c[0]), "+f"(c[1]), "+f"(c[2]), "+f"(c[3])
        : "r"(a[0]), "r"(a[1]), "r"(a[2]), "r"(a[3]), "r"(b[0]), "r"(b[1]));
}
__device__ __forceinline__ float ex2f(float x) {
    float y;
    asm("ex2.approx.ftz.f32 %0, %1;" : "=f"(y) : "f"(x));
    return y;
}
__device__ __forceinline__ uint32_t packbf(float a, float b) {
    __nv_bfloat162 t = __floats2bfloat162_rn(a, b);
    return *reinterpret_cast<uint32_t*>(&t);
}

// ---------------------------------------------------------------------------
// fp32 -> bf16 hi/lo split (elementwise) — used for hs and weights
// ---------------------------------------------------------------------------
__global__ __launch_bounds__(256) void split_bf16(
    const float* __restrict__ x, __nv_bfloat16* __restrict__ h,
    __nv_bfloat16* __restrict__ l, int n4)
{
    int i = blockIdx.x * blockDim.x + threadIdx.x;
    if (i >= n4) return;
    float4 v = ((const float4*)x)[i];
    float vv[4] = {v.x, v.y, v.z, v.w};
    __nv_bfloat16 hh[4], ll[4];
#pragma unroll
    for (int j = 0; j < 4; j++) {
        hh[j] = __float2bfloat16(vv[j]);
        ll[j] = __float2bfloat16(vv[j] - __bfloat162float(hh[j]));
    }
    __nv_bfloat162* hp = (__nv_bfloat162*)(h + i * 4);
    __nv_bfloat162* lp = (__nv_bfloat162*)(l + i * 4);
    hp[0] = __nv_bfloat162(hh[0], hh[1]); hp[1] = __nv_bfloat162(hh[2], hh[3]);
    lp[0] = __nv_bfloat162(ll[0], ll[1]); lp[1] = __nv_bfloat162(ll[2], ll[3]);
}

// ---------------------------------------------------------------------------
// Shared GEMM tile config
// ---------------------------------------------------------------------------
#define TPITCH 80
#define TILE_B 10240
#define STAGE_B 40960
#define GEMM_SMEM_BYTES (2 * STAGE_B)

// ---------------------------------------------------------------------------
// Fused QKV GEMM (bf16x3). Grid (36, 16). bng<3584: Q; <4096: K; else V.
// Q,K epilogue: fp32. V epilogue: direct bf16 hi/lo split.
// ---------------------------------------------------------------------------
__global__ __launch_bounds__(256, 2) void gemm_qkv(
    const __nv_bfloat16* __restrict__ Ah, const __nv_bfloat16* __restrict__ Al,
    const __nv_bfloat16* __restrict__ WqH, const __nv_bfloat16* __restrict__ WqL,
    const __nv_bfloat16* __restrict__ WkH, const __nv_bfloat16* __restrict__ WkL,
    const __nv_bfloat16* __restrict__ WvH, const __nv_bfloat16* __restrict__ WvL,
    const float* __restrict__ bq, const float* __restrict__ bk,
    const float* __restrict__ bv,
    float* __restrict__ Qout, float* __restrict__ Kout,
    __nv_bfloat16* __restrict__ VhOut, __nv_bfloat16* __restrict__ VlOut)
{
    extern __shared__ __align__(128) char smem[];
    const uint32_t sb = smem_u32(smem);
    const int tid  = threadIdx.x;
    const int wid  = tid >> 5;
    const int lane = tid & 31;
    const int warp_m = wid & 3;
    const int warp_n = wid >> 2;
    const int bm  = blockIdx.y * 128;
    const int bng = blockIdx.x * 128;
    const int nk  = HID >> 5;

    // per-CTA output selection
    const __nv_bfloat16 *Bh, *Bl;
    const float* bias;
    float* Cf = nullptr;
    __nv_bfloat16 *Oh = nullptr, *Ol = nullptr;
    int Nout;
    if (bng < HID) {
        Bh = WqH + (size_t)bng * HID; Bl = WqL + (size_t)bng * HID;
        bias = bq + bng; Cf = Qout + bng; Nout = HID;
    } else if (bng < HID + DKV) {
        const int o = bng - HID;
        Bh = WkH + (size_t)o * HID; Bl = WkL + (size_t)o * HID;
        bias = bk + o; Cf = Kout + o; Nout = DKV;
    } else {
        const int o = bng - HID - DKV;
        Bh = WvH + (size_t)o * HID; Bl = WvL + (size_t)o * HID;
        bias = bv + o; Oh = VhOut + o; Ol = VlOut + o; Nout = DKV;
    }

    const __nv_bfloat16* base[4] = {Ah + (size_t)bm * HID, Al + (size_t)bm * HID,
                                    Bh, Bl};

    auto load_stage = [&](int s, int kb) {
#pragma unroll
        for (int i = 0; i < 8; ++i) {
            const int c    = (i << 8) + tid;
            const int tile = c >> 9;
            const int rem  = c & 511;
            const int r    = rem >> 2;
            const int j    = rem & 3;
            const __nv_bfloat16* g = base[tile] + (size_t)r * HID + kb + (j << 3);
            cp_async16(sb + s * STAGE_B + tile * TILE_B + r * TPITCH + (j << 4), g);
        }
    };

    float acc[2][8][4];
#pragma unroll
    for (int mt = 0; mt < 2; mt++)
#pragma unroll
        for (int nt = 0; nt < 8; nt++)
#pragma unroll
            for (int e = 0; e < 4; e++) acc[mt][nt][e] = 0.0f;

    load_stage(0, 0);
    cp_commit();

    const uint32_t a_off = (uint32_t)(warp_m * 32 + (lane & 15)) * TPITCH
                         + ((lane >> 4) << 4);
    const uint32_t b_n   = (uint32_t)(warp_n * 64 + ((lane >> 4) << 3) + (lane & 7));
    const uint32_t b_off = b_n * TPITCH + (((lane >> 3) & 1) << 4);

    for (int i = 0; i < nk; ++i) {
        const int s = i & 1;
        if (i + 1 < nk) {
            load_stage(s ^ 1, (i + 1) << 5);
            cp_commit();
            asm volatile("cp.async.wait_group 1;" ::: "memory");
        } else {
            asm volatile("cp.async.wait_group 0;" ::: "memory");
        }
        __syncthreads();

        const uint32_t st = sb + s * STAGE_B;
#pragma unroll
        for (int k16 = 0; k16 < 2; k16++) {
            const uint32_t kb16 = k16 << 5;
            uint32_t a[2][2][4];
            ldsm4(a[0][0], st + 0 * TILE_B + a_off + kb16);
            ldsm4(a[0][1], st + 0 * TILE_B + a_off + kb16 + 16 * TPITCH);
            ldsm4(a[1][0], st + 1 * TILE_B + a_off + kb16);
            ldsm4(a[1][1], st + 1 * TILE_B + a_off + kb16 + 16 * TPITCH);

            uint32_t b[4][4];
#pragma unroll
            for (int q = 0; q < 4; q++)
                ldsm4(b[q], st + 2 * TILE_B + b_off + kb16 + (uint32_t)q * 16 * TPITCH);
#pragma unroll
            for (int mt = 0; mt < 2; mt++)
#pragma unroll
                for (int nt = 0; nt < 8; nt++) {
                    mma16816(acc[mt][nt], a[0][mt], &b[nt >> 1][(nt & 1) * 2]);
                    mma16816(acc[mt][nt], a[1][mt], &b[nt >> 1][(nt & 1) * 2]);
                }
#pragma unroll
            for (int q = 0; q < 4; q++)
                ldsm4(b[q], st + 3 * TILE_B + b_off + kb16 + (uint32_t)q * 16 * TPITCH);
#pragma unroll
            for (int mt = 0; mt < 2; mt++)
#pragma unroll
                for (int nt = 0; nt < 8; nt++)
                    mma16816(acc[mt][nt], a[0][mt], &b[nt >> 1][(nt & 1) * 2]);
        }
        __syncthreads();
    }

    const int g  = lane >> 2;
    const int ti = lane & 3;
#pragma unroll
    for (int mt = 0; mt < 2; mt++) {
        const int row0 = bm + warp_m * 32 + mt * 16 + g;
#pragma unroll
        for (int nt = 0; nt < 8; nt++) {
            const int col = warp_n * 64 + nt * 8 + ti * 2;
            const float b0 = bias[col], b1 = bias[col + 1];
            float v00 = acc[mt][nt][0] + b0, v01 = acc[mt][nt][1] + b1;
            float v10 = acc[mt][nt][2] + b0, v11 = acc[mt][nt][3] + b1;
            if (Cf) {
                *(float2*)(Cf + (size_t)row0 * Nout + col)       = make_float2(v00, v01);
                *(float2*)(Cf + (size_t)(row0 + 8) * Nout + col) = make_float2(v10, v11);
            } else {
                float h00 = __bfloat162float(__float2bfloat16(v00));
                float h01 = __bfloat162float(__float2bfloat16(v01));
                float h10 = __bfloat162float(__float2bfloat16(v10));
                float h11 = __bfloat162float(__float2bfloat16(v11));
                *(uint32_t*)(Oh + (size_t)row0 * Nout + col)       = packbf(h00, h01);
                *(uint32_t*)(Oh + (size_t)(row0 + 8) * Nout + col) = packbf(h10, h11);
                *(uint32_t*)(Ol + (size_t)row0 * Nout + col)       = packbf(v00 - h00, v01 - h01);
                *(uint32_t*)(Ol + (size_t)(row0 + 8) * Nout + col) = packbf(v10 - h10, v11 - h11);
            }
        }
    }
}

// ---------------------------------------------------------------------------
// bf16x3 HMMA GEMM (generic, fp32 out) — used for O projection
// ---------------------------------------------------------------------------
__global__ __launch_bounds__(256, 2) void gemm_bf16x3(
    const __nv_bfloat16* __restrict__ Ah, const __nv_bfloat16* __restrict__ Al,
    const __nv_bfloat16* __restrict__ Bh, const __nv_bfloat16* __restrict__ Bl,
    const float* __restrict__ bias, float* __restrict__ C,
    int M, int N, int K)
{
    extern __shared__ __align__(128) char smem[];
    const uint32_t sb = smem_u32(smem);
    const int tid  = threadIdx.x;
    const int wid  = tid >> 5;
    const int lane = tid & 31;
    const int warp_m = wid & 3;
    const int warp_n = wid >> 2;
    const int bm = blockIdx.y * 128;
    const int bn = blockIdx.x * 128;
    const int nk = K >> 5;

    const __nv_bfloat16* base[4] = {Ah + (size_t)bm * K, Al + (size_t)bm * K,
                                    Bh + (size_t)bn * K, Bl + (size_t)bn * K};

    auto load_stage = [&](int s, int kb) {
#pragma unroll
        for (int i = 0; i < 8; ++i) {
            const int c    = (i << 8) + tid;
            const int tile = c >> 9;
            const int rem  = c & 511;
            const int r    = rem >> 2;
            const int j    = rem & 3;
            const __nv_bfloat16* g = base[tile] + (size_t)r * K + kb + (j << 3);
            cp_async16(sb + s * STAGE_B + tile * TILE_B + r * TPITCH + (j << 4), g);
        }
    };

    float acc[2][8][4];
#pragma unroll
    for (int mt = 0; mt < 2; mt++)
#pragma unroll
        for (int nt = 0; nt < 8; nt++)
#pragma unroll
            for (int e = 0; e < 4; e++) acc[mt][nt][e] = 0.0f;

    load_stage(0, 0);
    cp_commit();

    const uint32_t a_off = (uint32_t)(warp_m * 32 + (lane & 15)) * TPITCH
                         + ((lane >> 4) << 4);
    const uint32_t b_n   = (uint32_t)(warp_n * 64 + ((lane >> 4) << 3) + (lane & 7));
    const uint32_t b_off = b_n * TPITCH + (((lane >> 3) & 1) << 4);

    for (int i = 0; i < nk; ++i) {
        const int s = i & 1;
        if (i + 1 < nk) {
            load_stage(s ^ 1, (i + 1) << 5);
            cp_commit();
            asm volatile("cp.async.wait_group 1;" ::: "memory");
        } else {
            asm volatile("cp.async.wait_group 0;" ::: "memory");
        }
        __syncthreads();

        const uint32_t st = sb + s * STAGE_B;
#pragma unroll
        for (int k16 = 0; k16 < 2; k16++) {
            const uint32_t kb16 = k16 << 5;
            uint32_t a[2][2][4];
            ldsm4(a[0][0], st + 0 * TILE_B + a_off + kb16);
            ldsm4(a[0][1], st + 0 * TILE_B + a_off + kb16 + 16 * TPITCH);
            ldsm4(a[1][0], st + 1 * TILE_B + a_off + kb16);
            ldsm4(a[1][1], st + 1 * TILE_B + a_off + kb16 + 16 * TPITCH);

            uint32_t b[4][4];
#pragma unroll
            for (int q = 0; q < 4; q++)
                ldsm4(b[q], st + 2 * TILE_B + b_off + kb16 + (uint32_t)q * 16 * TPITCH);
#pragma unroll
            for (int mt = 0; mt < 2; mt++)
#pragma unroll
                for (int nt = 0; nt < 8; nt++) {
                    mma16816(acc[mt][nt], a[0][mt], &b[nt >> 1][(nt & 1) * 2]);
                    mma16816(acc[mt][nt], a[1][mt], &b[nt >> 1][(nt & 1) * 2]);
                }
#pragma unroll
            for (int q = 0; q < 4; q++)
                ldsm4(b[q], st + 3 * TILE_B + b_off + kb16 + (uint32_t)q * 16 * TPITCH);
#pragma unroll
            for (int mt = 0; mt < 2; mt++)
#pragma unroll
                for (int nt = 0; nt < 8; nt++)
                    mma16816(acc[mt][nt], a[0][mt], &b[nt >> 1][(nt & 1) * 2]);
        }
        __syncthreads();
    }

    const int g  = lane >> 2;
    const int ti = lane & 3;
#pragma unroll
    for (int mt = 0; mt < 2; mt++) {
        const int row0 = bm + warp_m * 32 + mt * 16 + g;
#pragma unroll
        for (int nt = 0; nt < 8; nt++) {
            const int col = bn + warp_n * 64 + nt * 8 + ti * 2;
            float b0 = bias ? bias[col]     : 0.0f;
            float b1 = bias ? bias[col + 1] : 0.0f;
            float2 v0 = {acc[mt][nt][0] + b0, acc[mt][nt][1] + b1};
            float2 v1 = {acc[mt][nt][2] + b0, acc[mt][nt][3] + b1};
            *(float2*)(C + (size_t)row0 * N + col)       = v0;
            *(float2*)(C + (size_t)(row0 + 8) * N + col) = v1;
        }
    }
}

// ---------------------------------------------------------------------------
// RoPE + direct hi/lo split (no fp32 write-back, no separate split launches)
// ---------------------------------------------------------------------------
__global__ __launch_bounds__(256) void rope_split(
    const float* __restrict__ Qf, const float* __restrict__ Kf,
    const float* __restrict__ cosb, const float* __restrict__ sinb,
    __nv_bfloat16* __restrict__ qh, __nv_bfloat16* __restrict__ ql,
    __nv_bfloat16* __restrict__ kh, __nv_bfloat16* __restrict__ kl)
{
    const int s = blockIdx.x;
    const float* cs = cosb + (size_t)s * DH;
    const float* sn = sinb + (size_t)s * DH;
    const int tid = threadIdx.x;
    for (int i = tid; i < 32 * 64; i += 256) {
        const int head = i >> 6;
        const int d = i & 63;
        size_t off;
        const float* p;
        __nv_bfloat16 *oh, *ol;
        if (head < NHQ) {
            off = (size_t)s * HID + head * DH;
            p = Qf + off; oh = qh + off; ol = ql + off;
        } else {
            off = (size_t)s * DKV + (head - NHQ) * DH;
            p = Kf + off; oh = kh + off; ol = kl + off;
        }
        const float c1 = cs[d], c2 = cs[d + 64];
        const float s1 = sn[d], s2 = sn[d + 64];
        const float x1 = p[d], x2 = p[d + 64];
        const float y1 = x1 * c1 - x2 * s1;
        const float y2 = x2 * c2 + x1 * s2;
        const __nv_bfloat16 h1 = __float2bfloat16(y1);
        const __nv_bfloat16 h2 = __float2bfloat16(y2);
        oh[d]      = h1;
        oh[d + 64] = h2;
        ol[d]      = __float2bfloat16(y1 - __bfloat162float(h1));
        ol[d + 64] = __float2bfloat16(y2 - __bfloat162float(h2));
    }
}

// ---------------------------------------------------------------------------
// HMMA bf16x3 causal flash attention. Grid (16, 28), 256 thr.
// qb reversed for load balance; epilogue emits hi/lo bf16 AO directly.
// ---------------------------------------------------------------------------
#define APITCH 272
#define QHALF  34816
#define KVSTG  69632
#define ATTN_SMEM_BYTES (QHALF * 2 + KVSTG * 2)   // 208896

__global__ __launch_bounds__(256, 1) void attn_hmma(
    const __nv_bfloat16* __restrict__ qh_, const __nv_bfloat16* __restrict__ ql_,
    const __nv_bfloat16* __restrict__ kh_, const __nv_bfloat16* __restrict__ kl_,
    const __nv_bfloat16* __restrict__ vh_, const __nv_bfloat16* __restrict__ vl_,
    __nv_bfloat16* __restrict__ aoh, __nv_bfloat16* __restrict__ aol)
{
    extern __shared__ __align__(128) char smem[];
    const uint32_t sb = smem_u32(smem);
    const int tid  = threadIdx.x;
    const int wid  = tid >> 5;
    const int lane = tid & 31;
    const int qb = gridDim.x - 1 - blockIdx.x;     // big tiles first
    const int h  = blockIdx.y;
    const int kvh = h / N_REP;
    const int q0 = qb * 128;
    const int m0 = wid * 16;
    const int nkt = 2 * qb + 2;
    const float kscale = 0.08838834764831845f * 1.4426950408889634f;

#pragma unroll
    for (int it = 0; it < 16; ++it) {
        int idx = it * 256 + tid;
        int half = idx >> 11, rem = idx & 2047;
        int r = rem >> 4, c = rem & 15;
        const __nv_bfloat16* src =
            (half ? ql_ : qh_) + (size_t)(q0 + r) * HID + h * DH + c * 8;
        cp_async16(sb + half * QHALF + r * APITCH + c * 16, src);
    }
    cp_commit();

    auto load_kv = [&](int s, int kt) {
        const int k0 = kt * 64;
        const __nv_bfloat16* srcs[4] = {kh_, kl_, vh_, vl_};
#pragma unroll
        for (int it = 0; it < 16; ++it) {
            int idx = it * 256 + tid;
            int tz = idx >> 10, rem = idx & 1023;
            int r = rem >> 4, c = rem & 15;
            const __nv_bfloat16* src =
                srcs[tz] + (size_t)(k0 + r) * DKV + kvh * DH + c * 8;
            cp_async16(sb + 2 * QHALF + s * KVSTG + tz * 17408 + r * APITCH + c * 16,
                       src);
        }
        cp_commit();
    };
    load_kv(0, 0);

    float oacc[16][4];
#pragma unroll
    for (int f = 0; f < 16; f++)
#pragma unroll
        for (int e = 0; e < 4; e++) oacc[f][e] = 0.0f;
    float m_lo = -1e30f, m_hi = -1e30f, l_lo = 0.0f, l_hi = 0.0f;

    const uint32_t a_q   = sb + (uint32_t)(m0 + (lane & 15)) * APITCH
                         + ((lane >> 4) << 4);
    const uint32_t bkrow = ((lane >> 4) << 3) + (lane & 7);
    const uint32_t bkoff = (((lane >> 3) & 1) << 4);
    const uint32_t vrow  = (lane & 15);
    const uint32_t vcoff = ((lane >> 4) << 4);
    const int row_off  = lane >> 2;
    const int col_base = (lane & 3) * 2;
    const int row_lo_g = q0 + m0 + row_off;
    const int row_hi_g = row_lo_g + 8;

    for (int kt = 0; kt < nkt; ++kt) {
        const int s  = kt & 1;
        const int k0 = kt * 64;
        if (kt + 1 < nkt) {
            load_kv(s ^ 1, kt + 1);
            asm volatile("cp.async.wait_group 1;" ::: "memory");
        } else {
            asm volatile("cp.async.wait_group 0;" ::: "memory");
        }
        __syncthreads();

        const uint32_t kvb = sb + 2 * QHALF + s * KVSTG;
        const uint32_t khb = kvb, klb = kvb + 17408;
        const uint32_t vhb = kvb + 34816, vlb = kvb + 52224;

        float sacc[8][4];
#pragma unroll
        for (int f = 0; f < 8; f++)
#pragma unroll
            for (int e = 0; e < 4; e++) sacc[f][e] = 0.0f;

#pragma unroll
        for (int k16 = 0; k16 < 8; k16++) {
            uint32_t ah[4], al[4], bt[4];
            ldsm4(ah, a_q + k16 * 32);
            ldsm4(al, a_q + QHALF + k16 * 32);
#pragma unroll
            for (int g = 0; g < 4; g++) {
                const uint32_t baddr =
                    (uint32_t)(16 * g + bkrow) * APITCH + bkoff + k16 * 32;
                ldsm4(bt, khb + baddr);
                mma16816(sacc[2 * g],     ah, bt);
                mma16816(sacc[2 * g + 1], ah, bt + 2);
                mma16816(sacc[2 * g],     al, bt);
                mma16816(sacc[2 * g + 1], al, bt + 2);
                ldsm4(bt, klb + baddr);
                mma16816(sacc[2 * g],     ah, bt);
                mma16816(sacc[2 * g + 1], ah, bt + 2);
            }
        }

        const bool flag = (k0 + 63 > q0);
        float tmx_lo = -1e30f, tmx_hi = -1e30f;
#pragma unroll
        for (int f = 0; f < 8; f++) {
            const int c0g = k0 + 8 * f + col_base;
#pragma unroll
            for (int j = 0; j < 2; j++) {
                float x = sacc[f][j] * kscale;
                if (flag && (c0g + j > row_lo_g)) x = -1e30f;
                sacc[f][j] = x;
                tmx_lo = fmaxf(tmx_lo, x);
                float y = sacc[f][j + 2] * kscale;
                if (flag && (c0g + j > row_hi_g)) y = -1e30f;
                sacc[f][j + 2] = y;
                tmx_hi = fmaxf(tmx_hi, y);
            }
        }
        tmx_lo = fmaxf(tmx_lo, __shfl_xor_sync(0xffffffffu, tmx_lo, 1));
        tmx_lo = fmaxf(tmx_lo, __shfl_xor_sync(0xffffffffu, tmx_lo, 2));
        tmx_hi = fmaxf(tmx_hi, __shfl_xor_sync(0xffffffffu, tmx_hi, 1));
        tmx_hi = fmaxf(tmx_hi, __shfl_xor_sync(0xffffffffu, tmx_hi, 2));

        const float mn_lo = fmaxf(m_lo, tmx_lo);
        const float mn_hi = fmaxf(m_hi, tmx_hi);
        const float al_lo = ex2f(m_lo - mn_lo);
        const float al_hi = ex2f(m_hi - mn_hi);
        m_lo = mn_lo; m_hi = mn_hi;

        uint32_t Ph[16], Pl[16];
        float ps_lo = 0.0f, ps_hi = 0.0f;
#pragma unroll
        for (int f = 0; f < 8; f++) {
            float p0 = ex2f(sacc[f][0] - m_lo);
            float p1 = ex2f(sacc[f][1] - m_lo);
            float p2 = ex2f(sacc[f][2] - m_hi);
            float p3 = ex2f(sacc[f][3] - m_hi);
            ps_lo += p0 + p1; ps_hi += p2 + p3;
            float h0 = __bfloat162float(__float2bfloat16(p0));
            float h1 = __bfloat162float(__float2bfloat16(p1));
            float h2 = __bfloat162float(__float2bfloat16(p2));
            float h3 = __bfloat162float(__float2bfloat16(p3));
            const int c  = f >> 1;
            const int rb = (f & 1) * 2;
            Ph[c * 4 + rb]     = packbf(h0, h1);
            Ph[c * 4 + rb + 1] = packbf(h2, h3);
            Pl[c * 4 + rb]     = packbf(p0 - h0, p1 - h1);
            Pl[c * 4 + rb + 1] = packbf(p2 - h2, p3 - h3);
        }
        ps_lo += __shfl_xor_sync(0xffffffffu, ps_lo, 1);
        ps_lo += __shfl_xor_sync(0xffffffffu, ps_lo, 2);
        ps_hi += __shfl_xor_sync(0xffffffffu, ps_hi, 1);
        ps_hi += __shfl_xor_sync(0xffffffffu, ps_hi, 2);
        l_lo = l_lo * al_lo + ps_lo;
        l_hi = l_hi * al_hi + ps_hi;

#pragma unroll
        for (int f = 0; f < 16; f++) {
            oacc[f][0] *= al_lo; oacc[f][1] *= al_lo;
            oacc[f][2] *= al_hi; oacc[f][3] *= al_hi;
        }

#pragma unroll
        for (int c = 0; c < 4; c++) {
#pragma unroll
            for (int g = 0; g < 8; g++) {
                const uint32_t baddr =
                    (uint32_t)(16 * c + vrow) * APITCH + 32 * g + vcoff;
                uint32_t bt[4];
                ldsm4t(bt, vhb + baddr);
                mma16816(oacc[2 * g],     &Ph[c * 4], bt);
                mma16816(oacc[2 * g + 1], &Ph[c * 4], bt + 2);
                mma16816(oacc[2 * g],     &Pl[c * 4], bt);
                mma16816(oacc[2 * g + 1], &Pl[c * 4], bt + 2);
                ldsm4t(bt, vlb + baddr);
                mma16816(oacc[2 * g],     &Ph[c * 4], bt);
                mma16816(oacc[2 * g + 1], &Ph[c * 4], bt + 2);
            }
        }
        __syncthreads();
    }

    // ---- normalize + direct hi/lo bf16 store ----
    const float inv_lo = 1.0f / l_lo;
    const float inv_hi = 1.0f / l_hi;
#pragma unroll
    for (int f = 0; f < 16; f++) {
        const int col = 8 * f + col_base;
        const size_t off_lo = (size_t)row_lo_g * HID + h * DH + col;
        const size_t off_hi = (size_t)row_hi_g * HID + h * DH + col;
        float o0 = oacc[f][0] * inv_lo, o1 = oacc[f][1] * inv_lo;
        float o2 = oacc[f][2] * inv_hi, o3 = oacc[f][3] * inv_hi;
        float h0 = __bfloat162float(__float2bfloat16(o0));
        float h1 = __bfloat162float(__float2bfloat16(o1));
        float h2 = __bfloat162float(__float2bfloat16(o2));
        float h3 = __bfloat162float(__float2bfloat16(o3));
        *(uint32_t*)(aoh + off_lo) = packbf(h0, h1);
        *(uint32_t*)(aoh + off_hi) = packbf(h2, h3);
        *(uint32_t*)(aol + off_lo) = packbf(o0 - h0, o1 - h1);
        *(uint32_t*)(aol + off_hi) = packbf(o2 - h2, o3 - h3);
    }
}

// ---------------------------------------------------------------------------
// Launch
// ---------------------------------------------------------------------------
static void run_split(const float* x, __nv_bfloat16* h, __nv_bfloat16* l, int n) {
    int n4 = n / 4;
    split_bf16<<<(n4 + 255) / 256, 256>>>(x, h, l, n4);
}

extern "C" void kernel_launch(void* const* d_in, const int* in_sizes, int n_in,
                              void* d_out, int out_size)
{
    const float* hs   = (const float*)d_in[0];
    const float* Wq   = (const float*)d_in[1];
    const float* bq   = (const float*)d_in[2];
    const float* Wk   = (const float*)d_in[3];
    const float* bk   = (const float*)d_in[4];
    const float* Wv   = (const float*)d_in[5];
    const float* bv   = (const float*)d_in[6];
    const float* Wo   = (const float*)d_in[7];
    const float* cosb = (const float*)d_in[8];
    const float* sinb = (const float*)d_in[9];
    float* out = (float*)d_out;

    float *Qp, *Kp;
    cudaGetSymbolAddress((void**)&Qp, g_Q);
    cudaGetSymbolAddress((void**)&Kp, g_K);

    __nv_bfloat16 *hsh, *hsl, *aoh, *aol, *wqh, *wql, *wkh, *wkl, *wvh, *wvl, *woh, *wol;
    __nv_bfloat16 *qh, *ql, *kh, *kl, *vh, *vl;
    cudaGetSymbolAddress((void**)&hsh, g_hs_h); cudaGetSymbolAddress((void**)&hsl, g_hs_l);
    cudaGetSymbolAddress((void**)&aoh, g_ao_h); cudaGetSymbolAddress((void**)&aol, g_ao_l);
    cudaGetSymbolAddress((void**)&wqh, g_wq_h); cudaGetSymbolAddress((void**)&wql, g_wq_l);
    cudaGetSymbolAddress((void**)&wkh, g_wk_h); cudaGetSymbolAddress((void**)&wkl, g_wk_l);
    cudaGetSymbolAddress((void**)&wvh, g_wv_h); cudaGetSymbolAddress((void**)&wvl, g_wv_l);
    cudaGetSymbolAddress((void**)&woh, g_wo_h); cudaGetSymbolAddress((void**)&wol, g_wo_l);
    cudaGetSymbolAddress((void**)&qh, g_q_h);   cudaGetSymbolAddress((void**)&ql, g_q_l);
    cudaGetSymbolAddress((void**)&kh, g_k_h);   cudaGetSymbolAddress((void**)&kl, g_k_l);
    cudaGetSymbolAddress((void**)&vh, g_v_h);   cudaGetSymbolAddress((void**)&vl, g_v_l);

    cudaFuncSetAttribute(gemm_qkv, cudaFuncAttributeMaxDynamicSharedMemorySize,
                         GEMM_SMEM_BYTES);
    cudaFuncSetAttribute(gemm_bf16x3, cudaFuncAttributeMaxDynamicSharedMemorySize,
                         GEMM_SMEM_BYTES);
    cudaFuncSetAttribute(attn_hmma, cudaFuncAttributeMaxDynamicSharedMemorySize,
                         ATTN_SMEM_BYTES);

    // fp32 -> bf16 hi/lo splits (input + weights only)
    run_split(hs, hsh, hsl, S_LEN * HID);
    run_split(Wq, wqh, wql, HID * HID);
    run_split(Wk, wkh, wkl, DKV * HID);
    run_split(Wv, wvh, wvl, DKV * HID);
    run_split(Wo, woh, wol, HID * HID);

    // fused QKV projection: Q,K fp32 (pre-RoPE); V direct hi/lo bf16
    gemm_qkv<<<dim3((HID + 2 * DKV) / 128, S_LEN / 128), 256, GEMM_SMEM_BYTES>>>(
        hsh, hsl, wqh, wql, wkh, wkl, wvh, wvl, bq, bk, bv, Qp, Kp, vh, vl);

    // RoPE + direct hi/lo split of Q and K
    rope_split<<<S_LEN, 256>>>(Qp, Kp, cosb, sinb, qh, ql, kh, kl);

    attn_hmma<<<dim3(S_LEN / 128, NHQ), 256, ATTN_SMEM_BYTES>>>(
        qh, ql, kh, kl, vh, vl, aoh, aol);

    gemm_bf16x3<<<dim3(HID / 128, S_LEN / 128), 256, GEMM_SMEM_BYTES>>>(
        aoh, aol, woh, wol, nullptr, out, S_LEN, HID, HID);
}

// round 9
// speedup vs baseline: 3.7906x; 1.0049x over previous
#include <cuda_runtime.h>
#include <cuda_bf16.h>
#include <stdint.h>
#include <math.h>

#define S_LEN 2048
#define HID   3584
#define NHQ   28
#define NKV   4
#define DH    128
#define DKV   (NKV * DH)   // 512
#define N_REP (NHQ / NKV)  // 7

// ---------------- scratch (__device__ globals; no allocs allowed) ----------
__device__ float g_P1[S_LEN * HID];    // split-K partial for O projection

__device__ __nv_bfloat16 g_hs_h[S_LEN * HID],  g_hs_l[S_LEN * HID];
__device__ __nv_bfloat16 g_ao_h[S_LEN * HID],  g_ao_l[S_LEN * HID];
__device__ __nv_bfloat16 g_wq_h[HID * HID],    g_wq_l[HID * HID];
__device__ __nv_bfloat16 g_wo_h[HID * HID],    g_wo_l[HID * HID];
__device__ __nv_bfloat16 g_wk_h[DKV * HID],    g_wk_l[DKV * HID];
__device__ __nv_bfloat16 g_wv_h[DKV * HID],    g_wv_l[DKV * HID];

// post-RoPE bf16 splits for attention
__device__ __nv_bfloat16 g_q_h[S_LEN * HID],  g_q_l[S_LEN * HID];
__device__ __nv_bfloat16 g_k_h[S_LEN * DKV],  g_k_l[S_LEN * DKV];
__device__ __nv_bfloat16 g_v_h[S_LEN * DKV],  g_v_l[S_LEN * DKV];

// ---------------- PTX helpers ---------------------------------------------
__device__ __forceinline__ uint32_t smem_u32(const void* p) {
    uint32_t a;
    asm("{ .reg .u64 t; cvta.to.shared.u64 t, %1; cvt.u32.u64 %0, t; }"
        : "=r"(a) : "l"(p));
    return a;
}
__device__ __forceinline__ void cp_async16(uint32_t dst, const void* src) {
    asm volatile("cp.async.cg.shared.global [%0], [%1], 16;\n"
                 :: "r"(dst), "l"(src) : "memory");
}
__device__ __forceinline__ void cp_commit() {
    asm volatile("cp.async.commit_group;" ::: "memory");
}
__device__ __forceinline__ void ldsm4(uint32_t* r, uint32_t addr) {
    asm volatile("ldmatrix.sync.aligned.m8n8.x4.shared.b16 {%0,%1,%2,%3}, [%4];\n"
                 : "=r"(r[0]), "=r"(r[1]), "=r"(r[2]), "=r"(r[3]) : "r"(addr));
}
__device__ __forceinline__ void ldsm4t(uint32_t* r, uint32_t addr) {
    asm volatile("ldmatrix.sync.aligned.m8n8.x4.trans.shared.b16 {%0,%1,%2,%3}, [%4];\n"
                 : "=r"(r[0]), "=r"(r[1]), "=r"(r[2]), "=r"(r[3]) : "r"(addr));
}
__device__ __forceinline__ void mma16816(float* c, const uint32_t* a,
                                         const uint32_t* b) {
    asm volatile(
        "mma.sync.aligned.m16n8k16.row.col.f32.bf16.bf16.f32 "
        "{%0,%1,%2,%3}, {%4,%5,%6,%7}, {%8,%9}, {%0,%1,%2,%3};\n"
        : "+f"(c[0]), "+f"(c[1]), "+f"(c[2]), "+f"(c[3])
        : "r"(a[0]), "r"(a[1]), "r"(a[2]), "r"(a[3]), "r"(b[0]), "r"(b[1]));
}
__device__ __forceinline__ float ex2f(float x) {
    float y;
    asm("ex2.approx.ftz.f32 %0, %1;" : "=f"(y) : "f"(x));
    return y;
}
__device__ __forceinline__ uint32_t packbf(float a, float b) {
    __nv_bfloat162 t = __floats2bfloat162_rn(a, b);
    return *reinterpret_cast<uint32_t*>(&t);
}
// split two fp32 into packed bf16 hi pair + bf16 residual pair
__device__ __forceinline__ void split2(float p0, float p1,
                                       uint32_t& hi, uint32_t& lo) {
    const uint32_t h = packbf(p0, p1);
    const float h0 = __uint_as_float(h << 16);
    const float h1 = __uint_as_float(h & 0xFFFF0000u);
    lo = packbf(p0 - h0, p1 - h1);
    hi = h;
}

// ---------------------------------------------------------------------------
// One fused hi/lo split over hs + Wq + Wk + Wv + Wo (5 segments)
// ---------------------------------------------------------------------------
#define N4_HS (S_LEN * HID / 4)
#define N4_WQ (HID * HID / 4)
#define N4_WK (DKV * HID / 4)
#define SEG1 (N4_HS)
#define SEG2 (SEG1 + N4_WQ)
#define SEG3 (SEG2 + N4_WK)
#define SEG4 (SEG3 + N4_WK)
#define SEG5 (SEG4 + N4_WQ)

__global__ __launch_bounds__(256) void split5(
    const float* __restrict__ hs, const float* __restrict__ wq,
    const float* __restrict__ wk, const float* __restrict__ wv,
    const float* __restrict__ wo,
    __nv_bfloat16* __restrict__ hsh, __nv_bfloat16* __restrict__ hsl,
    __nv_bfloat16* __restrict__ wqh, __nv_bfloat16* __restrict__ wql,
    __nv_bfloat16* __restrict__ wkh, __nv_bfloat16* __restrict__ wkl,
    __nv_bfloat16* __restrict__ wvh, __nv_bfloat16* __restrict__ wvl,
    __nv_bfloat16* __restrict__ woh, __nv_bfloat16* __restrict__ wol)
{
    int i = blockIdx.x * blockDim.x + threadIdx.x;
    if (i >= SEG5) return;
    const float* x; __nv_bfloat16 *h, *l; int off;
    if (i < SEG1)      { x = hs; h = hsh; l = hsl; off = i; }
    else if (i < SEG2) { x = wq; h = wqh; l = wql; off = i - SEG1; }
    else if (i < SEG3) { x = wk; h = wkh; l = wkl; off = i - SEG2; }
    else if (i < SEG4) { x = wv; h = wvh; l = wvl; off = i - SEG3; }
    else               { x = wo; h = woh; l = wol; off = i - SEG4; }

    float4 v = ((const float4*)x)[off];
    uint32_t h01, l01, h23, l23;
    split2(v.x, v.y, h01, l01);
    split2(v.z, v.w, h23, l23);
    uint32_t* hp = (uint32_t*)(h + off * 4);
    uint32_t* lp = (uint32_t*)(l + off * 4);
    hp[0] = h01; hp[1] = h23;
    lp[0] = l01; lp[1] = l23;
}

// ---------------------------------------------------------------------------
// Shared GEMM tile config
// ---------------------------------------------------------------------------
#define TPITCH 80
#define TILE_B 10240
#define STAGE_B 40960
#define GEMM_SMEM_BYTES (2 * STAGE_B)
#define CPITCH 132

// ---------------------------------------------------------------------------
// Fused QKV GEMM (bf16x3) + fused RoPE. Grid (36, 16).
// bng<3584: Q (rope->hi/lo); <4096: K (rope->hi/lo); else V (direct hi/lo).
// ---------------------------------------------------------------------------
__global__ __launch_bounds__(256, 2) void gemm_qkv(
    const __nv_bfloat16* __restrict__ Ah, const __nv_bfloat16* __restrict__ Al,
    const __nv_bfloat16* __restrict__ WqH, const __nv_bfloat16* __restrict__ WqL,
    const __nv_bfloat16* __restrict__ WkH, const __nv_bfloat16* __restrict__ WkL,
    const __nv_bfloat16* __restrict__ WvH, const __nv_bfloat16* __restrict__ WvL,
    const float* __restrict__ bq, const float* __restrict__ bk,
    const float* __restrict__ bv,
    const float* __restrict__ cosb, const float* __restrict__ sinb,
    __nv_bfloat16* __restrict__ qh, __nv_bfloat16* __restrict__ ql,
    __nv_bfloat16* __restrict__ kh, __nv_bfloat16* __restrict__ kl,
    __nv_bfloat16* __restrict__ vhO, __nv_bfloat16* __restrict__ vlO)
{
    extern __shared__ __align__(128) char smem[];
    const uint32_t sb = smem_u32(smem);
    const int tid  = threadIdx.x;
    const int wid  = tid >> 5;
    const int lane = tid & 31;
    const int warp_m = wid & 3;
    const int warp_n = wid >> 2;
    const int bm  = blockIdx.y * 128;
    const int bng = blockIdx.x * 128;
    const int nk  = HID >> 5;

    const __nv_bfloat16 *Bh, *Bl;
    const float* bias;
    if (bng < HID) {
        Bh = WqH + (size_t)bng * HID; Bl = WqL + (size_t)bng * HID; bias = bq + bng;
    } else if (bng < HID + DKV) {
        const int o = bng - HID;
        Bh = WkH + (size_t)o * HID; Bl = WkL + (size_t)o * HID; bias = bk + o;
    } else {
        const int o = bng - HID - DKV;
        Bh = WvH + (size_t)o * HID; Bl = WvL + (size_t)o * HID; bias = bv + o;
    }

    const __nv_bfloat16* base[4] = {Ah + (size_t)bm * HID, Al + (size_t)bm * HID,
                                    Bh, Bl};

    auto load_stage = [&](int s, int kb) {
#pragma unroll
        for (int i = 0; i < 8; ++i) {
            const int c    = (i << 8) + tid;
            const int tile = c >> 9;
            const int rem  = c & 511;
            const int r    = rem >> 2;
            const int j    = rem & 3;
            const __nv_bfloat16* g = base[tile] + (size_t)r * HID + kb + (j << 3);
            cp_async16(sb + s * STAGE_B + tile * TILE_B + r * TPITCH + (j << 4), g);
        }
    };

    float acc[2][8][4];
#pragma unroll
    for (int mt = 0; mt < 2; mt++)
#pragma unroll
        for (int nt = 0; nt < 8; nt++)
#pragma unroll
            for (int e = 0; e < 4; e++) acc[mt][nt][e] = 0.0f;

    load_stage(0, 0);
    cp_commit();

    const uint32_t a_off = (uint32_t)(warp_m * 32 + (lane & 15)) * TPITCH
                         + ((lane >> 4) << 4);
    const uint32_t b_n   = (uint32_t)(warp_n * 64 + ((lane >> 4) << 3) + (lane & 7));
    const uint32_t b_off = b_n * TPITCH + (((lane >> 3) & 1) << 4);

    for (int i = 0; i < nk; ++i) {
        const int s = i & 1;
        if (i + 1 < nk) {
            load_stage(s ^ 1, (i + 1) << 5);
            cp_commit();
            asm volatile("cp.async.wait_group 1;" ::: "memory");
        } else {
            asm volatile("cp.async.wait_group 0;" ::: "memory");
        }
        __syncthreads();

        const uint32_t st = sb + s * STAGE_B;
#pragma unroll
        for (int k16 = 0; k16 < 2; k16++) {
            const uint32_t kb16 = k16 << 5;
            uint32_t a[2][2][4];
            ldsm4(a[0][0], st + 0 * TILE_B + a_off + kb16);
            ldsm4(a[0][1], st + 0 * TILE_B + a_off + kb16 + 16 * TPITCH);
            ldsm4(a[1][0], st + 1 * TILE_B + a_off + kb16);
            ldsm4(a[1][1], st + 1 * TILE_B + a_off + kb16 + 16 * TPITCH);

            uint32_t b[4][4];
#pragma unroll
            for (int q = 0; q < 4; q++)
                ldsm4(b[q], st + 2 * TILE_B + b_off + kb16 + (uint32_t)q * 16 * TPITCH);
#pragma unroll
            for (int mt = 0; mt < 2; mt++)
#pragma unroll
                for (int nt = 0; nt < 8; nt++) {
                    mma16816(acc[mt][nt], a[0][mt], &b[nt >> 1][(nt & 1) * 2]);
                    mma16816(acc[mt][nt], a[1][mt], &b[nt >> 1][(nt & 1) * 2]);
                }
#pragma unroll
            for (int q = 0; q < 4; q++)
                ldsm4(b[q], st + 3 * TILE_B + b_off + kb16 + (uint32_t)q * 16 * TPITCH);
#pragma unroll
            for (int mt = 0; mt < 2; mt++)
#pragma unroll
                for (int nt = 0; nt < 8; nt++)
                    mma16816(acc[mt][nt], a[0][mt], &b[nt >> 1][(nt & 1) * 2]);
        }
        __syncthreads();
    }

    const int g  = lane >> 2;
    const int ti = lane & 3;

    if (bng >= HID + DKV) {
        // ---- V epilogue: direct bf16 hi/lo ----
        const int o = bng - HID - DKV;
        __nv_bfloat16* Oh = vhO + o;
        __nv_bfloat16* Ol = vlO + o;
#pragma unroll
        for (int mt = 0; mt < 2; mt++) {
            const int row0 = bm + warp_m * 32 + mt * 16 + g;
#pragma unroll
            for (int nt = 0; nt < 8; nt++) {
                const int col = warp_n * 64 + nt * 8 + ti * 2;
                const float b0 = bias[col], b1 = bias[col + 1];
                uint32_t h0, l0, h1, l1;
                split2(acc[mt][nt][0] + b0, acc[mt][nt][1] + b1, h0, l0);
                split2(acc[mt][nt][2] + b0, acc[mt][nt][3] + b1, h1, l1);
                *(uint32_t*)(Oh + (size_t)row0 * DKV + col)       = h0;
                *(uint32_t*)(Oh + (size_t)(row0 + 8) * DKV + col) = h1;
                *(uint32_t*)(Ol + (size_t)row0 * DKV + col)       = l0;
                *(uint32_t*)(Ol + (size_t)(row0 + 8) * DKV + col) = l1;
            }
        }
    } else {
        // ---- Q/K epilogue: stage to smem, apply RoPE, emit hi/lo ----
        float* cst = (float*)smem;
#pragma unroll
        for (int mt = 0; mt < 2; mt++) {
            const int r0 = warp_m * 32 + mt * 16 + g;
#pragma unroll
            for (int nt = 0; nt < 8; nt++) {
                const int col = warp_n * 64 + nt * 8 + ti * 2;
                const float b0 = bias[col], b1 = bias[col + 1];
                *(float2*)&cst[r0 * CPITCH + col] =
                    make_float2(acc[mt][nt][0] + b0, acc[mt][nt][1] + b1);
                *(float2*)&cst[(r0 + 8) * CPITCH + col] =
                    make_float2(acc[mt][nt][2] + b0, acc[mt][nt][3] + b1);
            }
        }
        __syncthreads();

        const bool isQ = (bng < HID);
        const int colbase = isQ ? bng : (bng - HID);
        const int nout = isQ ? HID : DKV;
        __nv_bfloat16* oh = isQ ? qh : kh;
        __nv_bfloat16* ol = isQ ? ql : kl;

        const int rsub = tid >> 6;          // 0..3
        const int d    = tid & 63;          // 0..63
#pragma unroll 4
        for (int it = 0; it < 32; ++it) {
            const int r  = it * 4 + rsub;
            const int sg = bm + r;
            const float x1 = cst[r * CPITCH + d];
            const float x2 = cst[r * CPITCH + 64 + d];
            const float c1 = cosb[(size_t)sg * DH + d];
            const float c2 = cosb[(size_t)sg * DH + 64 + d];
            const float s1 = sinb[(size_t)sg * DH + d];
            const float s2 = sinb[(size_t)sg * DH + 64 + d];
            const float y1 = x1 * c1 - x2 * s1;
            const float y2 = x2 * c2 + x1 * s2;
            const __nv_bfloat16 h1 = __float2bfloat16(y1);
            const __nv_bfloat16 h2 = __float2bfloat16(y2);
            const size_t ob = (size_t)sg * nout + colbase + d;
            oh[ob]      = h1;
            oh[ob + 64] = h2;
            ol[ob]      = __float2bfloat16(y1 - __bfloat162float(h1));
            ol[ob + 64] = __float2bfloat16(y2 - __bfloat162float(h2));
        }
    }
}

// ---------------------------------------------------------------------------
// Split-K(2) bf16x3 GEMM for O projection. Grid (28, 16, 2).
// z=0 writes Cp0, z=1 writes Cp1; host adds them after.
// ---------------------------------------------------------------------------
__global__ __launch_bounds__(256, 2) void gemm_osplit(
    const __nv_bfloat16* __restrict__ Ah, const __nv_bfloat16* __restrict__ Al,
    const __nv_bfloat16* __restrict__ Bh, const __nv_bfloat16* __restrict__ Bl,
    float* __restrict__ Cp0, float* __restrict__ Cp1)
{
    extern __shared__ __align__(128) char smem[];
    const uint32_t sb = smem_u32(smem);
    const int tid  = threadIdx.x;
    const int wid  = tid >> 5;
    const int lane = tid & 31;
    const int warp_m = wid & 3;
    const int warp_n = wid >> 2;
    const int bm = blockIdx.y * 128;
    const int bn = blockIdx.x * 128;
    const int kz = blockIdx.z * (HID / 2);
    const int nk = (HID / 2) >> 5;   // 56
    float* Cw = blockIdx.z ? Cp1 : Cp0;

    const __nv_bfloat16* base[4] = {Ah + (size_t)bm * HID + kz,
                                    Al + (size_t)bm * HID + kz,
                                    Bh + (size_t)bn * HID + kz,
                                    Bl + (size_t)bn * HID + kz};

    auto load_stage = [&](int s, int kb) {
#pragma unroll
        for (int i = 0; i < 8; ++i) {
            const int c    = (i << 8) + tid;
            const int tile = c >> 9;
            const int rem  = c & 511;
            const int r    = rem >> 2;
            const int j    = rem & 3;
            const __nv_bfloat16* g = base[tile] + (size_t)r * HID + kb + (j << 3);
            cp_async16(sb + s * STAGE_B + tile * TILE_B + r * TPITCH + (j << 4), g);
        }
    };

    float acc[2][8][4];
#pragma unroll
    for (int mt = 0; mt < 2; mt++)
#pragma unroll
        for (int nt = 0; nt < 8; nt++)
#pragma unroll
            for (int e = 0; e < 4; e++) acc[mt][nt][e] = 0.0f;

    load_stage(0, 0);
    cp_commit();

    const uint32_t a_off = (uint32_t)(warp_m * 32 + (lane & 15)) * TPITCH
                         + ((lane >> 4) << 4);
    const uint32_t b_n   = (uint32_t)(warp_n * 64 + ((lane >> 4) << 3) + (lane & 7));
    const uint32_t b_off = b_n * TPITCH + (((lane >> 3) & 1) << 4);

    for (int i = 0; i < nk; ++i) {
        const int s = i & 1;
        if (i + 1 < nk) {
            load_stage(s ^ 1, (i + 1) << 5);
            cp_commit();
            asm volatile("cp.async.wait_group 1;" ::: "memory");
        } else {
            asm volatile("cp.async.wait_group 0;" ::: "memory");
        }
        __syncthreads();

        const uint32_t st = sb + s * STAGE_B;
#pragma unroll
        for (int k16 = 0; k16 < 2; k16++) {
            const uint32_t kb16 = k16 << 5;
            uint32_t a[2][2][4];
            ldsm4(a[0][0], st + 0 * TILE_B + a_off + kb16);
            ldsm4(a[0][1], st + 0 * TILE_B + a_off + kb16 + 16 * TPITCH);
            ldsm4(a[1][0], st + 1 * TILE_B + a_off + kb16);
            ldsm4(a[1][1], st + 1 * TILE_B + a_off + kb16 + 16 * TPITCH);

            uint32_t b[4][4];
#pragma unroll
            for (int q = 0; q < 4; q++)
                ldsm4(b[q], st + 2 * TILE_B + b_off + kb16 + (uint32_t)q * 16 * TPITCH);
#pragma unroll
            for (int mt = 0; mt < 2; mt++)
#pragma unroll
                for (int nt = 0; nt < 8; nt++) {
                    mma16816(acc[mt][nt], a[0][mt], &b[nt >> 1][(nt & 1) * 2]);
                    mma16816(acc[mt][nt], a[1][mt], &b[nt >> 1][(nt & 1) * 2]);
                }
#pragma unroll
            for (int q = 0; q < 4; q++)
                ldsm4(b[q], st + 3 * TILE_B + b_off + kb16 + (uint32_t)q * 16 * TPITCH);
#pragma unroll
            for (int mt = 0; mt < 2; mt++)
#pragma unroll
                for (int nt = 0; nt < 8; nt++)
                    mma16816(acc[mt][nt], a[0][mt], &b[nt >> 1][(nt & 1) * 2]);
        }
        __syncthreads();
    }

    const int g  = lane >> 2;
    const int ti = lane & 3;
#pragma unroll
    for (int mt = 0; mt < 2; mt++) {
        const int row0 = bm + warp_m * 32 + mt * 16 + g;
#pragma unroll
        for (int nt = 0; nt < 8; nt++) {
            const int col = bn + warp_n * 64 + nt * 8 + ti * 2;
            *(float2*)(Cw + (size_t)row0 * HID + col) =
                make_float2(acc[mt][nt][0], acc[mt][nt][1]);
            *(float2*)(Cw + (size_t)(row0 + 8) * HID + col) =
                make_float2(acc[mt][nt][2], acc[mt][nt][3]);
        }
    }
}

// out += partial
__global__ __launch_bounds__(256) void add_f4(
    float* __restrict__ o, const float* __restrict__ p, int n4)
{
    int i = blockIdx.x * blockDim.x + threadIdx.x;
    if (i >= n4) return;
    float4 a = ((float4*)o)[i];
    float4 b = ((const float4*)p)[i];
    a.x += b.x; a.y += b.y; a.z += b.z; a.w += b.w;
    ((float4*)o)[i] = a;
}

// ---------------------------------------------------------------------------
// HMMA bf16x3 causal flash attention. Grid (16, 28), 256 thr.
// ---------------------------------------------------------------------------
#define APITCH 272
#define QHALF  34816
#define KVSTG  69632
#define ATTN_SMEM_BYTES (QHALF * 2 + KVSTG * 2)   // 208896

__global__ __launch_bounds__(256, 1) void attn_hmma(
    const __nv_bfloat16* __restrict__ qh_, const __nv_bfloat16* __restrict__ ql_,
    const __nv_bfloat16* __restrict__ kh_, const __nv_bfloat16* __restrict__ kl_,
    const __nv_bfloat16* __restrict__ vh_, const __nv_bfloat16* __restrict__ vl_,
    __nv_bfloat16* __restrict__ aoh, __nv_bfloat16* __restrict__ aol)
{
    extern __shared__ __align__(128) char smem[];
    const uint32_t sb = smem_u32(smem);
    const int tid  = threadIdx.x;
    const int wid  = tid >> 5;
    const int lane = tid & 31;
    const int qb = gridDim.x - 1 - blockIdx.x;     // big tiles first
    const int h  = blockIdx.y;
    const int kvh = h / N_REP;
    const int q0 = qb * 128;
    const int m0 = wid * 16;
    const int nkt = 2 * qb + 2;
    const float kscale = 0.08838834764831845f * 1.4426950408889634f;

#pragma unroll
    for (int it = 0; it < 16; ++it) {
        int idx = it * 256 + tid;
        int half = idx >> 11, rem = idx & 2047;
        int r = rem >> 4, c = rem & 15;
        const __nv_bfloat16* src =
            (half ? ql_ : qh_) + (size_t)(q0 + r) * HID + h * DH + c * 8;
        cp_async16(sb + half * QHALF + r * APITCH + c * 16, src);
    }
    cp_commit();

    auto load_kv = [&](int s, int kt) {
        const int k0 = kt * 64;
        const __nv_bfloat16* srcs[4] = {kh_, kl_, vh_, vl_};
#pragma unroll
        for (int it = 0; it < 16; ++it) {
            int idx = it * 256 + tid;
            int tz = idx >> 10, rem = idx & 1023;
            int r = rem >> 4, c = rem & 15;
            const __nv_bfloat16* src =
                srcs[tz] + (size_t)(k0 + r) * DKV + kvh * DH + c * 8;
            cp_async16(sb + 2 * QHALF + s * KVSTG + tz * 17408 + r * APITCH + c * 16,
                       src);
        }
        cp_commit();
    };
    load_kv(0, 0);

    float oacc[16][4];
#pragma unroll
    for (int f = 0; f < 16; f++)
#pragma unroll
        for (int e = 0; e < 4; e++) oacc[f][e] = 0.0f;
    float m_lo = -1e30f, m_hi = -1e30f, l_lo = 0.0f, l_hi = 0.0f;

    const uint32_t a_q   = sb + (uint32_t)(m0 + (lane & 15)) * APITCH
                         + ((lane >> 4) << 4);
    const uint32_t bkrow = ((lane >> 4) << 3) + (lane & 7);
    const uint32_t bkoff = (((lane >> 3) & 1) << 4);
    const uint32_t vrow  = (lane & 15);
    const uint32_t vcoff = ((lane >> 4) << 4);
    const int row_off  = lane >> 2;
    const int col_base = (lane & 3) * 2;
    const int row_lo_g = q0 + m0 + row_off;
    const int row_hi_g = row_lo_g + 8;

    for (int kt = 0; kt < nkt; ++kt) {
        const int s  = kt & 1;
        const int k0 = kt * 64;
        if (kt + 1 < nkt) {
            load_kv(s ^ 1, kt + 1);
            asm volatile("cp.async.wait_group 1;" ::: "memory");
        } else {
            asm volatile("cp.async.wait_group 0;" ::: "memory");
        }
        __syncthreads();

        const uint32_t kvb = sb + 2 * QHALF + s * KVSTG;
        const uint32_t khb = kvb, klb = kvb + 17408;
        const uint32_t vhb = kvb + 34816, vlb = kvb + 52224;

        float sacc[8][4];
#pragma unroll
        for (int f = 0; f < 8; f++)
#pragma unroll
            for (int e = 0; e < 4; e++) sacc[f][e] = 0.0f;

#pragma unroll
        for (int k16 = 0; k16 < 8; k16++) {
            uint32_t ah[4], al[4], bt[4];
            ldsm4(ah, a_q + k16 * 32);
            ldsm4(al, a_q + QHALF + k16 * 32);
#pragma unroll
            for (int g = 0; g < 4; g++) {
                const uint32_t baddr =
                    (uint32_t)(16 * g + bkrow) * APITCH + bkoff + k16 * 32;
                ldsm4(bt, khb + baddr);
                mma16816(sacc[2 * g],     ah, bt);
                mma16816(sacc[2 * g + 1], ah, bt + 2);
                mma16816(sacc[2 * g],     al, bt);
                mma16816(sacc[2 * g + 1], al, bt + 2);
                ldsm4(bt, klb + baddr);
                mma16816(sacc[2 * g],     ah, bt);
                mma16816(sacc[2 * g + 1], ah, bt + 2);
            }
        }

        const bool flag = (k0 + 63 > q0);
        float tmx_lo = -1e30f, tmx_hi = -1e30f;
#pragma unroll
        for (int f = 0; f < 8; f++) {
            const int c0g = k0 + 8 * f + col_base;
#pragma unroll
            for (int j = 0; j < 2; j++) {
                float x = sacc[f][j] * kscale;
                if (flag && (c0g + j > row_lo_g)) x = -1e30f;
                sacc[f][j] = x;
                tmx_lo = fmaxf(tmx_lo, x);
                float y = sacc[f][j + 2] * kscale;
                if (flag && (c0g + j > row_hi_g)) y = -1e30f;
                sacc[f][j + 2] = y;
                tmx_hi = fmaxf(tmx_hi, y);
            }
        }
        tmx_lo = fmaxf(tmx_lo, __shfl_xor_sync(0xffffffffu, tmx_lo, 1));
        tmx_lo = fmaxf(tmx_lo, __shfl_xor_sync(0xffffffffu, tmx_lo, 2));
        tmx_hi = fmaxf(tmx_hi, __shfl_xor_sync(0xffffffffu, tmx_hi, 1));
        tmx_hi = fmaxf(tmx_hi, __shfl_xor_sync(0xffffffffu, tmx_hi, 2));

        const float mn_lo = fmaxf(m_lo, tmx_lo);
        const float mn_hi = fmaxf(m_hi, tmx_hi);
        const float al_lo = ex2f(m_lo - mn_lo);
        const float al_hi = ex2f(m_hi - mn_hi);
        m_lo = mn_lo; m_hi = mn_hi;

        uint32_t Ph[16], Pl[16];
        float ps_lo = 0.0f, ps_hi = 0.0f;
#pragma unroll
        for (int f = 0; f < 8; f++) {
            float p0 = ex2f(sacc[f][0] - m_lo);
            float p1 = ex2f(sacc[f][1] - m_lo);
            float p2 = ex2f(sacc[f][2] - m_hi);
            float p3 = ex2f(sacc[f][3] - m_hi);
            ps_lo += p0 + p1; ps_hi += p2 + p3;
            const int c  = f >> 1;
            const int rb = (f & 1) * 2;
            split2(p0, p1, Ph[c * 4 + rb],     Pl[c * 4 + rb]);
            split2(p2, p3, Ph[c * 4 + rb + 1], Pl[c * 4 + rb + 1]);
        }
        ps_lo += __shfl_xor_sync(0xffffffffu, ps_lo, 1);
        ps_lo += __shfl_xor_sync(0xffffffffu, ps_lo, 2);
        ps_hi += __shfl_xor_sync(0xffffffffu, ps_hi, 1);
        ps_hi += __shfl_xor_sync(0xffffffffu, ps_hi, 2);
        l_lo = l_lo * al_lo + ps_lo;
        l_hi = l_hi * al_hi + ps_hi;

#pragma unroll
        for (int f = 0; f < 16; f++) {
            oacc[f][0] *= al_lo; oacc[f][1] *= al_lo;
            oacc[f][2] *= al_hi; oacc[f][3] *= al_hi;
        }

#pragma unroll
        for (int c = 0; c < 4; c++) {
#pragma unroll
            for (int g = 0; g < 8; g++) {
                const uint32_t baddr =
                    (uint32_t)(16 * c + vrow) * APITCH + 32 * g + vcoff;
                uint32_t bt[4];
                ldsm4t(bt, vhb + baddr);
                mma16816(oacc[2 * g],     &Ph[c * 4], bt);
                mma16816(oacc[2 * g + 1], &Ph[c * 4], bt + 2);
                mma16816(oacc[2 * g],     &Pl[c * 4], bt);
                mma16816(oacc[2 * g + 1], &Pl[c * 4], bt + 2);
                ldsm4t(bt, vlb + baddr);
                mma16816(oacc[2 * g],     &Ph[c * 4], bt);
                mma16816(oacc[2 * g + 1], &Ph[c * 4], bt + 2);
            }
        }
        __syncthreads();
    }

    // ---- normalize + direct hi/lo bf16 store ----
    const float inv_lo = 1.0f / l_lo;
    const float inv_hi = 1.0f / l_hi;
#pragma unroll
    for (int f = 0; f < 16; f++) {
        const int col = 8 * f + col_base;
        const size_t off_lo = (size_t)row_lo_g * HID + h * DH + col;
        const size_t off_hi = (size_t)row_hi_g * HID + h * DH + col;
        uint32_t h0, l0, h1, l1;
        split2(oacc[f][0] * inv_lo, oacc[f][1] * inv_lo, h0, l0);
        split2(oacc[f][2] * inv_hi, oacc[f][3] * inv_hi, h1, l1);
        *(uint32_t*)(aoh + off_lo) = h0;
        *(uint32_t*)(aoh + off_hi) = h1;
        *(uint32_t*)(aol + off_lo) = l0;
        *(uint32_t*)(aol + off_hi) = l1;
    }
}

// ---------------------------------------------------------------------------
// Launch
// ---------------------------------------------------------------------------
extern "C" void kernel_launch(void* const* d_in, const int* in_sizes, int n_in,
                              void* d_out, int out_size)
{
    const float* hs   = (const float*)d_in[0];
    const float* Wq   = (const float*)d_in[1];
    const float* bq   = (const float*)d_in[2];
    const float* Wk   = (const float*)d_in[3];
    const float* bk   = (const float*)d_in[4];
    const float* Wv   = (const float*)d_in[5];
    const float* bv   = (const float*)d_in[6];
    const float* Wo   = (const float*)d_in[7];
    const float* cosb = (const float*)d_in[8];
    const float* sinb = (const float*)d_in[9];
    float* out = (float*)d_out;

    float* P1;
    cudaGetSymbolAddress((void**)&P1, g_P1);

    __nv_bfloat16 *hsh, *hsl, *aoh, *aol, *wqh, *wql, *wkh, *wkl, *wvh, *wvl, *woh, *wol;
    __nv_bfloat16 *qh, *ql, *kh, *kl, *vh, *vl;
    cudaGetSymbolAddress((void**)&hsh, g_hs_h); cudaGetSymbolAddress((void**)&hsl, g_hs_l);
    cudaGetSymbolAddress((void**)&aoh, g_ao_h); cudaGetSymbolAddress((void**)&aol, g_ao_l);
    cudaGetSymbolAddress((void**)&wqh, g_wq_h); cudaGetSymbolAddress((void**)&wql, g_wq_l);
    cudaGetSymbolAddress((void**)&wkh, g_wk_h); cudaGetSymbolAddress((void**)&wkl, g_wk_l);
    cudaGetSymbolAddress((void**)&wvh, g_wv_h); cudaGetSymbolAddress((void**)&wvl, g_wv_l);
    cudaGetSymbolAddress((void**)&woh, g_wo_h); cudaGetSymbolAddress((void**)&wol, g_wo_l);
    cudaGetSymbolAddress((void**)&qh, g_q_h);   cudaGetSymbolAddress((void**)&ql, g_q_l);
    cudaGetSymbolAddress((void**)&kh, g_k_h);   cudaGetSymbolAddress((void**)&kl, g_k_l);
    cudaGetSymbolAddress((void**)&vh, g_v_h);   cudaGetSymbolAddress((void**)&vl, g_v_l);

    cudaFuncSetAttribute(gemm_qkv, cudaFuncAttributeMaxDynamicSharedMemorySize,
                         GEMM_SMEM_BYTES);
    cudaFuncSetAttribute(gemm_osplit, cudaFuncAttributeMaxDynamicSharedMemorySize,
                         GEMM_SMEM_BYTES);
    cudaFuncSetAttribute(attn_hmma, cudaFuncAttributeMaxDynamicSharedMemorySize,
                         ATTN_SMEM_BYTES);

    // single fused hi/lo split for hs + all weights
    split5<<<(SEG5 + 255) / 256, 256>>>(hs, Wq, Wk, Wv, Wo,
                                        hsh, hsl, wqh, wql, wkh, wkl,
                                        wvh, wvl, woh, wol);

    // fused QKV projection + RoPE: emits q/k/v hi-lo bf16 directly
    gemm_qkv<<<dim3((HID + 2 * DKV) / 128, S_LEN / 128), 256, GEMM_SMEM_BYTES>>>(
        hsh, hsl, wqh, wql, wkh, wkl, wvh, wvl, bq, bk, bv,
        cosb, sinb, qh, ql, kh, kl, vh, vl);

    attn_hmma<<<dim3(S_LEN / 128, NHQ), 256, ATTN_SMEM_BYTES>>>(
        qh, ql, kh, kl, vh, vl, aoh, aol);

    // split-K(2) O projection + reduction
    gemm_osplit<<<dim3(HID / 128, S_LEN / 128, 2), 256, GEMM_SMEM_BYTES>>>(
        aoh, aol, woh, wol, out, P1);
    add_f4<<<(S_LEN * HID / 4 + 255) / 256, 256>>>(out, P1, S_LEN * HID / 4);
}